// round 2
// baseline (speedup 1.0000x reference)
#include <cuda_runtime.h>
#include <math.h>
#include <stdint.h>

// Problem constants
#define B 512
#define N 100
#define D 128
#define H 8
#define DK 16
#define FF 512
#define TD 384          // 3*D
#define M_ROWS (B*N)    // 51200
#define NEGV -1e9f
#define CLIPV 10.0

static __device__ float g_h [ (size_t)M_ROWS * D ];     // hidden state
static __device__ float g_3d[ (size_t)M_ROWS * TD ];    // qkv / hp scratch
static __device__ float g_ff[ (size_t)M_ROWS * FF ];    // ff1 output
static __device__ float g_o [ (size_t)M_ROWS * D ];     // attention output
static __device__ float g_s [ (size_t)M_ROWS * D ];     // pre-BN (residual sum)
static __device__ double g_part[2][128*128];            // BN partial sums [p][c]
static __device__ double g_mean[D], g_rstd[D];
static __device__ float g_hm[B*D], g_fc[B*D];           // mean over n, fixed_ctx

// ---------------------------------------------------------------------------
// h = x @ init_W + init_b    (x:[B*N,2], W:[2,D])  (double math)
// ---------------------------------------------------------------------------
__global__ void init_embed_kernel(const float* __restrict__ x,
                                  const float* __restrict__ W,
                                  const float* __restrict__ bias) {
    int idx = blockIdx.x * blockDim.x + threadIdx.x;   // over M_ROWS*D
    if (idx >= M_ROWS * D) return;
    int i = idx >> 7, d = idx & 127;
    double v = (double)x[i*2] * (double)W[d]
             + (double)x[i*2+1] * (double)W[D + d]
             + (double)bias[d];
    g_h[idx] = (float)v;
}

// ---------------------------------------------------------------------------
// Tiled GEMM with fp64 accumulation: C[M,Nc] = A[M,K] @ W[K,Nc] (+bias)(+res)(relu)
// BM=BN=64, BK=16, 256 threads, 4x4 per thread (double acc).
// Requires M%64==0, Nc%64==0, K%16==0.
// ---------------------------------------------------------------------------
__global__ __launch_bounds__(256)
void gemm64_kernel(const float* __restrict__ A, const float* __restrict__ W,
                   const float* __restrict__ bias, const float* __restrict__ res,
                   float* __restrict__ C, int M, int K, int Nc, int relu) {
    __shared__ double As[16][64];
    __shared__ double Bs[16][68];
    const int tid = threadIdx.x;
    const int tx = tid & 15, ty = tid >> 4;
    const int row0 = blockIdx.y * 64, col0 = blockIdx.x * 64;
    const int ar = tid >> 2, ac = (tid & 3) * 4;     // A tile: 64 rows x 16 k
    const int br = tid >> 4, bc = (tid & 15) * 4;    // B tile: 16 k x 64 cols
    double acc[4][4];
#pragma unroll
    for (int i = 0; i < 4; i++)
#pragma unroll
        for (int j = 0; j < 4; j++) acc[i][j] = 0.0;

    for (int kt = 0; kt < K; kt += 16) {
        float4 av = *reinterpret_cast<const float4*>(&A[(size_t)(row0+ar)*K + kt + ac]);
        As[ac+0][ar] = (double)av.x; As[ac+1][ar] = (double)av.y;
        As[ac+2][ar] = (double)av.z; As[ac+3][ar] = (double)av.w;
        float4 bv = *reinterpret_cast<const float4*>(&W[(size_t)(kt+br)*Nc + col0 + bc]);
        Bs[br][bc+0] = (double)bv.x; Bs[br][bc+1] = (double)bv.y;
        Bs[br][bc+2] = (double)bv.z; Bs[br][bc+3] = (double)bv.w;
        __syncthreads();
#pragma unroll
        for (int k = 0; k < 16; k++) {
            double a[4], b[4];
#pragma unroll
            for (int i = 0; i < 4; i++) a[i] = As[k][ty*4 + i];
#pragma unroll
            for (int j = 0; j < 4; j++) b[j] = Bs[k][tx*4 + j];
#pragma unroll
            for (int i = 0; i < 4; i++)
#pragma unroll
                for (int j = 0; j < 4; j++) acc[i][j] = fma(a[i], b[j], acc[i][j]);
        }
        __syncthreads();
    }
#pragma unroll
    for (int i = 0; i < 4; i++) {
        int r = row0 + ty*4 + i;
#pragma unroll
        for (int j = 0; j < 4; j++) {
            int c = col0 + tx*4 + j;
            double v = acc[i][j];
            if (bias) v += (double)bias[c];
            if (res)  v += (double)res[(size_t)r*Nc + c];
            if (relu) v = v > 0.0 ? v : 0.0;
            C[(size_t)r*Nc + c] = (float)v;
        }
    }
}

// ---------------------------------------------------------------------------
// Fused MHA for encoder: qkv [B,N,3D] -> o [B,N,D].  One block per (b,h).
// Double accumulation + double exp.
// ---------------------------------------------------------------------------
__global__ __launch_bounds__(256)
void attn_kernel(const float* __restrict__ qkv, float* __restrict__ o) {
    int bh = blockIdx.x;
    int b = bh >> 3, hh = bh & 7;
    __shared__ float ksh[100*17];
    __shared__ float vsh[100*17];
    __shared__ float psh[8][100];
    int tid = threadIdx.x;
    for (int i = tid; i < 1600; i += 256) {
        int m = i >> 4, d = i & 15;
        const float* base = qkv + (size_t)(b*N + m) * TD + hh*16 + d;
        ksh[m*17 + d] = base[D];
        vsh[m*17 + d] = base[2*D];
    }
    __syncthreads();
    int w = tid >> 5, lane = tid & 31;
    for (int n = w; n < N; n += 8) {
        const float* qp = qkv + (size_t)(b*N + n) * TD + hh*16;
        double qreg[16];
#pragma unroll
        for (int d = 0; d < 16; d++) qreg[d] = (double)qp[d];
        double s[4];
        double mx = -1e30;
#pragma unroll
        for (int j = 0; j < 4; j++) {
            int m = lane + 32*j;
            if (m < N) {
                double a = 0.0;
#pragma unroll
                for (int d = 0; d < 16; d++) a = fma(qreg[d], (double)ksh[m*17 + d], a);
                s[j] = a * 0.25;   // 1/sqrt(DK)
                mx = fmax(mx, s[j]);
            } else s[j] = -1e30;
        }
#pragma unroll
        for (int off = 16; off; off >>= 1) mx = fmax(mx, __shfl_xor_sync(0xffffffffu, mx, off));
        double sum = 0.0;
#pragma unroll
        for (int j = 0; j < 4; j++) {
            int m = lane + 32*j;
            if (m < N) { s[j] = exp(s[j] - mx); sum += s[j]; }
        }
#pragma unroll
        for (int off = 16; off; off >>= 1) sum += __shfl_xor_sync(0xffffffffu, sum, off);
        double inv = 1.0 / sum;
#pragma unroll
        for (int j = 0; j < 4; j++) {
            int m = lane + 32*j;
            if (m < N) psh[w][m] = (float)(s[j] * inv);
        }
        __syncwarp();
        if (lane < 16) {
            double a = 0.0;
            for (int m = 0; m < N; m++) a = fma((double)psh[w][m], (double)vsh[m*17 + lane], a);
            o[(size_t)(b*N + n) * D + hh*16 + lane] = (float)a;
        }
        __syncwarp();
    }
}

// ---------------------------------------------------------------------------
// BatchNorm (training mode). Two-stage deterministic reduction, double sums.
// ---------------------------------------------------------------------------
__global__ void bn_stats1_kernel(const float* __restrict__ s) {
    __shared__ double ssum[256], ssq[256];
    int p = blockIdx.x, tid = threadIdx.x;
    int c = tid & 127, roff = tid >> 7;
    double a = 0.0, q = 0.0;
    size_t base = (size_t)p * 400 * D;
    for (int r = roff; r < 400; r += 2) {
        double v = (double)s[base + (size_t)r * D + c];
        a += v; q = fma(v, v, q);
    }
    ssum[tid] = a; ssq[tid] = q;
    __syncthreads();
    if (tid < 128) {
        g_part[0][p*128 + tid] = ssum[tid] + ssum[tid+128];
        g_part[1][p*128 + tid] = ssq[tid]  + ssq[tid+128];
    }
}
__global__ void bn_stats2_kernel() {
    int c = threadIdx.x;
    double a = 0.0, q = 0.0;
    for (int p = 0; p < 128; p++) { a += g_part[0][p*128 + c]; q += g_part[1][p*128 + c]; }
    double mean = a * (1.0 / (double)M_ROWS);
    double var  = q * (1.0 / (double)M_ROWS) - mean*mean;
    g_mean[c] = mean;
    g_rstd[c] = 1.0 / sqrt(var + 1e-5);
}
__global__ void bn_apply_kernel(const float* __restrict__ s, const float* __restrict__ gb,
                                float* __restrict__ h) {
    int idx = blockIdx.x * blockDim.x + threadIdx.x;
    if (idx >= M_ROWS * D) return;
    int d = idx & 127;
    double v = (double)gb[d] * ((double)s[idx] - g_mean[d]) * g_rstd[d] + (double)gb[D + d];
    h[idx] = (float)v;
}

// ---------------------------------------------------------------------------
// Decoder precompute: hm = mean_n(h); fixed_ctx = hm @ proj_fixed_W
// ---------------------------------------------------------------------------
__global__ void meann_kernel() {
    int b = blockIdx.x, d = threadIdx.x;
    double a = 0.0;
    for (int n = 0; n < N; n++) a += (double)g_h[(size_t)(b*N + n) * D + d];
    g_hm[b*D + d] = (float)(a * (1.0 / (double)N));
}
__global__ void fixedctx_kernel(const float* __restrict__ Wf) {
    __shared__ float sh[D];
    int b = blockIdx.x, d = threadIdx.x;
    sh[d] = g_hm[b*D + d];
    __syncthreads();
    double a = 0.0;
    for (int k = 0; k < D; k++) a = fma((double)sh[k], (double)Wf[k*D + d], a);
    g_fc[b*D + d] = (float)a;
}

// ---------------------------------------------------------------------------
// Persistent greedy pointer decode: one block per batch element, 100 steps.
// Double accumulation + double transcendentals; tensors stored fp32 in smem.
// Writes out[b]=cost, out[512+b]=ll, out[1024 + b*100 + s]=pi (as float).
// ---------------------------------------------------------------------------
#define HPS 385                 // padded row stride for hp in smem
#define DEC_SMEM_FLOATS (N*HPS + D*D + D + 2*D + D + H*N + D + D + 104)
#define DEC_SMEM_BYTES  (16 + DEC_SMEM_FLOATS*4 + 204*4)

__global__ __launch_bounds__(128)
void decode_kernel(const float* __restrict__ x,
                   const float* __restrict__ Wph,
                   const float* __restrict__ Wstep,
                   const float* __restrict__ Wout,
                   float* __restrict__ out) {
    extern __shared__ double dsm[];
    double* sh_ll  = dsm;                   // [1] running log-likelihood
    float* sh_hp   = (float*)(dsm + 2);     // N*385
    float* sh_wout = sh_hp + N*HPS;         // 16384
    float* sh_fc   = sh_wout + D*D;         // 128
    float* sh_ctx  = sh_fc + D;             // 256
    float* sh_q    = sh_ctx + 2*D;          // 128
    float* sh_c    = sh_q + D;              // 800
    float* sh_g    = sh_c + H*N;            // 128
    float* sh_g2   = sh_g + D;              // 128
    float* sh_lg   = sh_g2 + D;             // 104
    int*   sh_mask = (int*)(sh_lg + 104);   // 100
    int*   sh_pi   = sh_mask + 100;         // 100
    int*   sh_ctrl = sh_pi + 100;           // first, prev

    const double NF = 0.08838834764831843;  // 1/sqrt(D)
    int b = blockIdx.x, tid = threadIdx.x;
    int w = tid >> 5, lane = tid & 31;

    for (int i = tid; i < N*TD; i += 128) {
        int n = i / TD, j = i - n*TD;
        sh_hp[n*HPS + j] = g_3d[(size_t)b * (N*TD) + i];
    }
    for (int i = tid; i < D*D; i += 128) sh_wout[i] = Wout[i];
    sh_fc[tid] = g_fc[b*D + tid];
    for (int n = tid; n < N; n += 128) sh_mask[n] = 0;
    if (tid == 0) { sh_ll[0] = 0.0; sh_ctrl[0] = 0; sh_ctrl[1] = 0; }
    __syncthreads();

    for (int s = 0; s < N; s++) {
        // 1. context vector (2D)
        if (s == 0) {
            sh_ctx[tid]     = Wph[tid];
            sh_ctx[D + tid] = Wph[D + tid];
        } else {
            int fa = sh_ctrl[0], pa = sh_ctrl[1];
            sh_ctx[tid]     = g_h[(size_t)(b*N + fa) * D + tid];
            sh_ctx[D + tid] = g_h[(size_t)(b*N + pa) * D + tid];
        }
        __syncthreads();
        // 2. q = fixed_ctx + ctx @ Wstep  (double accum)
        {
            double qv = (double)sh_fc[tid];
            for (int k = 0; k < 2*D; k++)
                qv = fma((double)sh_ctx[k], (double)Wstep[k*D + tid], qv);
            sh_q[tid] = (float)qv;
        }
        __syncthreads();
        // 3. compat [H,N] (masked, *nf)
        for (int idx = tid; idx < H*N; idx += 128) {
            int hh = idx / N, n = idx - hh*N;
            const float* kp = sh_hp + n*HPS + hh*16;
            const float* qp = sh_q + hh*16;
            double a = 0.0;
#pragma unroll
            for (int d = 0; d < 16; d++) a = fma((double)qp[d], (double)kp[d], a);
            sh_c[idx] = sh_mask[n] ? NEGV : (float)(a * NF);
        }
        __syncthreads();
        // 4. per-head softmax (in place), 4 warps x 2 heads, double exp
        for (int rep = 0; rep < 2; rep++) {
            int head = w*2 + rep;
            double mx = -1e30;
            for (int n = lane; n < N; n += 32) mx = fmax(mx, (double)sh_c[head*N + n]);
#pragma unroll
            for (int off = 16; off; off >>= 1) mx = fmax(mx, __shfl_xor_sync(0xffffffffu, mx, off));
            double sum = 0.0;
            double ev[4];
#pragma unroll
            for (int j = 0; j < 4; j++) {
                int n = lane + 32*j;
                if (n < N) { ev[j] = exp((double)sh_c[head*N + n] - mx); sum += ev[j]; }
                else ev[j] = 0.0;
            }
#pragma unroll
            for (int off = 16; off; off >>= 1) sum += __shfl_xor_sync(0xffffffffu, sum, off);
            double inv = 1.0 / sum;
#pragma unroll
            for (int j = 0; j < 4; j++) {
                int n = lane + 32*j;
                if (n < N) sh_c[head*N + n] = (float)(ev[j] * inv);
            }
        }
        __syncthreads();
        // 5. glimpse g[h,dk]
        {
            int hh = tid >> 4;
            const float* pp = sh_c + hh*N;
            const float* vp = sh_hp + D + tid;
            double a = 0.0;
            for (int n = 0; n < N; n++) a = fma((double)pp[n], (double)vp[n*HPS], a);
            sh_g[tid] = (float)a;
        }
        __syncthreads();
        // 6. glimpse @ proj_out_W
        {
            double a = 0.0;
            for (int k = 0; k < D; k++) a = fma((double)sh_g[k], (double)sh_wout[k*D + tid], a);
            sh_g2[tid] = (float)a;
        }
        __syncthreads();
        // 7. logits over nodes (double tanh)
        if (tid < N) {
            const float* lp = sh_hp + tid*HPS + 2*D;
            double a = 0.0;
            for (int d = 0; d < D; d++) a = fma((double)sh_g2[d], (double)lp[d], a);
            sh_lg[tid] = sh_mask[tid] ? NEGV : (float)(tanh(a * NF) * CLIPV);
        }
        __syncthreads();
        // 8. argmax (first-max) + logsumexp, warp 0
        if (w == 0) {
            float mx = -1e30f; int mi = N + 1;
            for (int n = lane; n < N; n += 32) {
                float v = sh_lg[n];
                if (v > mx) { mx = v; mi = n; }
            }
#pragma unroll
            for (int off = 16; off; off >>= 1) {
                float om = __shfl_xor_sync(0xffffffffu, mx, off);
                int   oi = __shfl_xor_sync(0xffffffffu, mi, off);
                if (om > mx || (om == mx && oi < mi)) { mx = om; mi = oi; }
            }
            double sum = 0.0;
            for (int n = lane; n < N; n += 32) sum += exp((double)sh_lg[n] - (double)mx);
#pragma unroll
            for (int off = 16; off; off >>= 1) sum += __shfl_xor_sync(0xffffffffu, sum, off);
            if (lane == 0) {
                double lse = (double)mx + log(sum);
                sh_ll[0] += (double)sh_lg[mi] - lse;
                sh_mask[mi] = 1;
                sh_ctrl[1] = mi;
                if (s == 0) sh_ctrl[0] = mi;
                sh_pi[s] = mi;
                out[2*B + b*N + s] = (float)mi;
            }
        }
        __syncthreads();
    }
    // tour cost (closed cycle), double sqrt/sum
    if (tid < N) {
        int a = sh_pi[tid], c = sh_pi[(tid + 1) % N];
        double dx = (double)x[(b*N + a)*2]     - (double)x[(b*N + c)*2];
        double dy = (double)x[(b*N + a)*2 + 1] - (double)x[(b*N + c)*2 + 1];
        sh_lg[tid] = (float)sqrt(dx*dx + dy*dy);
    }
    __syncthreads();
    if (tid == 0) {
        double cst = 0.0;
        for (int t = 0; t < N; t++) cst += (double)sh_lg[t];
        out[b] = (float)cst;
        out[B + b] = (float)sh_ll[0];
    }
}

// ---------------------------------------------------------------------------
extern "C" void kernel_launch(void* const* d_in, const int* in_sizes, int n_in,
                              void* d_out, int out_size) {
    const float* x        = (const float*)d_in[0];   // [B,N,2]
    const float* init_W   = (const float*)d_in[1];   // [2,D]
    const float* init_b   = (const float*)d_in[2];   // [D]
    const float* qkv_W    = (const float*)d_in[3];   // [L,D,3D]
    const float* out_W    = (const float*)d_in[4];   // [L,D,D]
    const float* bn1      = (const float*)d_in[5];   // [L,2,D]
    const float* bn2      = (const float*)d_in[6];   // [L,2,D]
    const float* ff1_W    = (const float*)d_in[7];   // [L,D,FF]
    const float* ff1_b    = (const float*)d_in[8];   // [L,FF]
    const float* ff2_W    = (const float*)d_in[9];   // [L,FF,D]
    const float* ff2_b    = (const float*)d_in[10];  // [L,D]
    const float* Wph      = (const float*)d_in[11];  // [2D]
    const float* nodes_W  = (const float*)d_in[12];  // [D,3D]
    const float* fixed_W  = (const float*)d_in[13];  // [D,D]
    const float* step_W   = (const float*)d_in[14];  // [2D,D]
    const float* pout_W   = (const float*)d_in[15];  // [D,D]
    float* out = (float*)d_out;

    cudaFuncSetAttribute(decode_kernel, cudaFuncAttributeMaxDynamicSharedMemorySize,
                         DEC_SMEM_BYTES + 256);

    float *p_h, *p_3d, *p_ff, *p_o, *p_s;
    cudaGetSymbolAddress((void**)&p_h,  g_h);
    cudaGetSymbolAddress((void**)&p_3d, g_3d);
    cudaGetSymbolAddress((void**)&p_ff, g_ff);
    cudaGetSymbolAddress((void**)&p_o,  g_o);
    cudaGetSymbolAddress((void**)&p_s,  g_s);

    const int EW = 256;
    int egrid = (M_ROWS * D + EW - 1) / EW;

    init_embed_kernel<<<egrid, EW>>>(x, init_W, init_b);

    for (int l = 0; l < 2; l++) {
        // qkv = h @ W_qkv[l]
        gemm64_kernel<<<dim3(TD/64, M_ROWS/64), 256>>>(
            p_h, qkv_W + (size_t)l*D*TD, nullptr, nullptr, p_3d, M_ROWS, D, TD, 0);
        // fused MHA
        attn_kernel<<<B*H, 256>>>(p_3d, p_o);
        // s = o @ out_W + h  (residual)
        gemm64_kernel<<<dim3(D/64, M_ROWS/64), 256>>>(
            p_o, out_W + (size_t)l*D*D, nullptr, p_h, p_s, M_ROWS, D, D, 0);
        bn_stats1_kernel<<<128, 256>>>(p_s);
        bn_stats2_kernel<<<1, 128>>>();
        bn_apply_kernel<<<egrid, EW>>>(p_s, bn1 + (size_t)l*2*D, p_h);
        // ff1 = relu(h @ W1 + b1)
        gemm64_kernel<<<dim3(FF/64, M_ROWS/64), 256>>>(
            p_h, ff1_W + (size_t)l*D*FF, ff1_b + (size_t)l*FF, nullptr, p_ff, M_ROWS, D, FF, 1);
        // s = ff1 @ W2 + b2 + h
        gemm64_kernel<<<dim3(D/64, M_ROWS/64), 256>>>(
            p_ff, ff2_W + (size_t)l*FF*D, ff2_b + (size_t)l*D, p_h, p_s, M_ROWS, FF, D, 0);
        bn_stats1_kernel<<<128, 256>>>(p_s);
        bn_stats2_kernel<<<1, 128>>>();
        bn_apply_kernel<<<egrid, EW>>>(p_s, bn2 + (size_t)l*2*D, p_h);
    }

    // decoder precompute
    gemm64_kernel<<<dim3(TD/64, M_ROWS/64), 256>>>(
        p_h, nodes_W, nullptr, nullptr, p_3d, M_ROWS, D, TD, 0);
    meann_kernel<<<B, D>>>();
    fixedctx_kernel<<<B, D>>>(fixed_W);

    // persistent greedy decode (all 100 steps inside one kernel)
    decode_kernel<<<B, 128, DEC_SMEM_BYTES + 256>>>(x, Wph, step_W, pout_W, out);
}

// round 3
// speedup vs baseline: 1.4379x; 1.4379x over previous
#include <cuda_runtime.h>
#include <math.h>
#include <stdint.h>

// Problem constants
#define B 512
#define N 100
#define D 128
#define H 8
#define DK 16
#define FF 512
#define TD 384          // 3*D
#define M_ROWS (B*N)    // 51200
#define NEGV -1e9f
#define CLIPV 10.0

static __device__ float g_h [ (size_t)M_ROWS * D ];     // hidden state
static __device__ float g_3d[ (size_t)M_ROWS * TD ];    // qkv / hp scratch
static __device__ float g_ff[ (size_t)M_ROWS * FF ];    // ff1 output
static __device__ float g_o [ (size_t)M_ROWS * D ];     // attention output
static __device__ float g_s [ (size_t)M_ROWS * D ];     // pre-BN (residual sum)
static __device__ double g_part[2][128*128];            // BN partial sums [p][c]
static __device__ double g_mean[D], g_rstd[D];
static __device__ float g_hm[B*D], g_fc[B*D];           // mean over n, fixed_ctx

// ---------------------------------------------------------------------------
// h = x @ init_W + init_b
// ---------------------------------------------------------------------------
__global__ void init_embed_kernel(const float* __restrict__ x,
                                  const float* __restrict__ W,
                                  const float* __restrict__ bias) {
    int idx = blockIdx.x * blockDim.x + threadIdx.x;
    if (idx >= M_ROWS * D) return;
    int i = idx >> 7, d = idx & 127;
    double v = (double)x[i*2] * (double)W[d]
             + (double)x[i*2+1] * (double)W[D + d]
             + (double)bias[d];
    g_h[idx] = (float)v;
}

// ---------------------------------------------------------------------------
// Tiled GEMM, fp64 accumulation. BM=128, BN=64, BK=16, 256 threads,
// 8x4 strided thread tile. Conflict-free smem reads, coalesced global loads.
// ---------------------------------------------------------------------------
#define AS_STRIDE 129
#define BS_STRIDE 65
__global__ __launch_bounds__(256, 2)
void gemm64_kernel(const float* __restrict__ A, const float* __restrict__ W,
                   const float* __restrict__ bias, const float* __restrict__ res,
                   float* __restrict__ C, int M, int K, int Nc, int relu) {
    __shared__ double As[16 * AS_STRIDE];   // 16.5 KB
    __shared__ double Bs[16 * BS_STRIDE];   // 8.3 KB
    const int tid = threadIdx.x;
    const int tx = tid & 15, ty = tid >> 4;
    const int row0 = blockIdx.y * 128, col0 = blockIdx.x * 64;
    const int ar = tid >> 2, ac = (tid & 3) * 4;     // A loader: 64 rows/pass, 4 f4 cols
    const int bk = tid >> 4, bc = (tid & 15) * 4;    // B loader: 16 k rows, 16 f4 cols
    double acc[8][4];
#pragma unroll
    for (int i = 0; i < 8; i++)
#pragma unroll
        for (int j = 0; j < 4; j++) acc[i][j] = 0.0;

    for (int kt = 0; kt < K; kt += 16) {
        float4 a0 = *reinterpret_cast<const float4*>(&A[(size_t)(row0+ar)*K + kt + ac]);
        float4 a1 = *reinterpret_cast<const float4*>(&A[(size_t)(row0+ar+64)*K + kt + ac]);
        float4 bv = *reinterpret_cast<const float4*>(&W[(size_t)(kt+bk)*Nc + col0 + bc]);
        As[(ac+0)*AS_STRIDE + ar] = (double)a0.x;
        As[(ac+1)*AS_STRIDE + ar] = (double)a0.y;
        As[(ac+2)*AS_STRIDE + ar] = (double)a0.z;
        As[(ac+3)*AS_STRIDE + ar] = (double)a0.w;
        As[(ac+0)*AS_STRIDE + ar+64] = (double)a1.x;
        As[(ac+1)*AS_STRIDE + ar+64] = (double)a1.y;
        As[(ac+2)*AS_STRIDE + ar+64] = (double)a1.z;
        As[(ac+3)*AS_STRIDE + ar+64] = (double)a1.w;
        Bs[bk*BS_STRIDE + bc+0] = (double)bv.x;
        Bs[bk*BS_STRIDE + bc+1] = (double)bv.y;
        Bs[bk*BS_STRIDE + bc+2] = (double)bv.z;
        Bs[bk*BS_STRIDE + bc+3] = (double)bv.w;
        __syncthreads();
#pragma unroll
        for (int k = 0; k < 16; k++) {
            double a[8], bb[4];
#pragma unroll
            for (int i = 0; i < 8; i++) a[i] = As[k*AS_STRIDE + ty + 16*i];
#pragma unroll
            for (int j = 0; j < 4; j++) bb[j] = Bs[k*BS_STRIDE + tx + 16*j];
#pragma unroll
            for (int i = 0; i < 8; i++)
#pragma unroll
                for (int j = 0; j < 4; j++) acc[i][j] = fma(a[i], bb[j], acc[i][j]);
        }
        __syncthreads();
    }
#pragma unroll
    for (int i = 0; i < 8; i++) {
        int r = row0 + ty + 16*i;
#pragma unroll
        for (int j = 0; j < 4; j++) {
            int c = col0 + tx + 16*j;
            double v = acc[i][j];
            if (bias) v += (double)bias[c];
            if (res)  v += (double)res[(size_t)r*Nc + c];
            if (relu) v = v > 0.0 ? v : 0.0;
            C[(size_t)r*Nc + c] = (float)v;
        }
    }
}

// ---------------------------------------------------------------------------
// Fused MHA: qkv [B,N,3D] -> o [B,N,D]. One block per (b,h). Double math, ILP.
// ---------------------------------------------------------------------------
__global__ __launch_bounds__(256)
void attn_kernel(const float* __restrict__ qkv, float* __restrict__ o) {
    int bh = blockIdx.x;
    int b = bh >> 3, hh = bh & 7;
    __shared__ float ksh[100*17];
    __shared__ float vsh[100*17];
    __shared__ float psh[8][100];
    int tid = threadIdx.x;
    for (int i = tid; i < 1600; i += 256) {
        int m = i >> 4, d = i & 15;
        const float* base = qkv + (size_t)(b*N + m) * TD + hh*16 + d;
        ksh[m*17 + d] = base[D];
        vsh[m*17 + d] = base[2*D];
    }
    __syncthreads();
    int w = tid >> 5, lane = tid & 31;
    for (int n = w; n < N; n += 8) {
        const float* qp = qkv + (size_t)(b*N + n) * TD + hh*16;
        double qreg[16];
#pragma unroll
        for (int d = 0; d < 16; d++) qreg[d] = (double)qp[d];
        double s[4];
        double mx = -1e30;
#pragma unroll
        for (int j = 0; j < 4; j++) {
            int m = lane + 32*j;
            if (m < N) {
                double a0 = 0.0, a1 = 0.0;
#pragma unroll
                for (int d = 0; d < 16; d += 2) {
                    a0 = fma(qreg[d],   (double)ksh[m*17 + d],   a0);
                    a1 = fma(qreg[d+1], (double)ksh[m*17 + d+1], a1);
                }
                s[j] = (a0 + a1) * 0.25;
                mx = fmax(mx, s[j]);
            } else s[j] = -1e30;
        }
#pragma unroll
        for (int off = 16; off; off >>= 1) mx = fmax(mx, __shfl_xor_sync(0xffffffffu, mx, off));
        double sum = 0.0;
#pragma unroll
        for (int j = 0; j < 4; j++) {
            int m = lane + 32*j;
            if (m < N) { s[j] = exp(s[j] - mx); sum += s[j]; }
        }
#pragma unroll
        for (int off = 16; off; off >>= 1) sum += __shfl_xor_sync(0xffffffffu, sum, off);
        double inv = 1.0 / sum;
#pragma unroll
        for (int j = 0; j < 4; j++) {
            int m = lane + 32*j;
            if (m < N) psh[w][m] = (float)(s[j] * inv);
        }
        __syncwarp();
        if (lane < 16) {
            double a0 = 0.0, a1 = 0.0, a2 = 0.0, a3 = 0.0;
            for (int m = 0; m < 100; m += 4) {
                a0 = fma((double)psh[w][m],   (double)vsh[(m)*17 + lane],   a0);
                a1 = fma((double)psh[w][m+1], (double)vsh[(m+1)*17 + lane], a1);
                a2 = fma((double)psh[w][m+2], (double)vsh[(m+2)*17 + lane], a2);
                a3 = fma((double)psh[w][m+3], (double)vsh[(m+3)*17 + lane], a3);
            }
            o[(size_t)(b*N + n) * D + hh*16 + lane] = (float)((a0+a1)+(a2+a3));
        }
        __syncwarp();
    }
}

// ---------------------------------------------------------------------------
// BatchNorm (training mode), two-stage deterministic reduction (double).
// ---------------------------------------------------------------------------
__global__ void bn_stats1_kernel(const float* __restrict__ s) {
    __shared__ double ssum[256], ssq[256];
    int p = blockIdx.x, tid = threadIdx.x;
    int c = tid & 127, roff = tid >> 7;
    double a = 0.0, q = 0.0;
    size_t base = (size_t)p * 400 * D;
    for (int r = roff; r < 400; r += 2) {
        double v = (double)s[base + (size_t)r * D + c];
        a += v; q = fma(v, v, q);
    }
    ssum[tid] = a; ssq[tid] = q;
    __syncthreads();
    if (tid < 128) {
        g_part[0][p*128 + tid] = ssum[tid] + ssum[tid+128];
        g_part[1][p*128 + tid] = ssq[tid]  + ssq[tid+128];
    }
}
__global__ void bn_stats2_kernel() {
    int c = threadIdx.x;
    double a = 0.0, q = 0.0;
    for (int p = 0; p < 128; p++) { a += g_part[0][p*128 + c]; q += g_part[1][p*128 + c]; }
    double mean = a * (1.0 / (double)M_ROWS);
    double var  = q * (1.0 / (double)M_ROWS) - mean*mean;
    g_mean[c] = mean;
    g_rstd[c] = 1.0 / sqrt(var + 1e-5);
}
__global__ void bn_apply_kernel(const float* __restrict__ s, const float* __restrict__ gb,
                                float* __restrict__ h) {
    int idx = blockIdx.x * blockDim.x + threadIdx.x;
    if (idx >= M_ROWS * D) return;
    int d = idx & 127;
    double v = (double)gb[d] * ((double)s[idx] - g_mean[d]) * g_rstd[d] + (double)gb[D + d];
    h[idx] = (float)v;
}

// ---------------------------------------------------------------------------
// Decoder precompute
// ---------------------------------------------------------------------------
__global__ void meann_kernel() {
    int b = blockIdx.x, d = threadIdx.x;
    double a = 0.0;
    for (int n = 0; n < N; n++) a += (double)g_h[(size_t)(b*N + n) * D + d];
    g_hm[b*D + d] = (float)(a * (1.0 / (double)N));
}
__global__ void fixedctx_kernel(const float* __restrict__ Wf) {
    __shared__ float sh[D];
    int b = blockIdx.x, d = threadIdx.x;
    sh[d] = g_hm[b*D + d];
    __syncthreads();
    double a = 0.0;
    for (int k = 0; k < D; k++) a = fma((double)sh[k], (double)Wf[k*D + d], a);
    g_fc[b*D + d] = (float)a;
}

// ---------------------------------------------------------------------------
// Persistent greedy pointer decode. 256 threads/block, 1 block per batch elt.
// All GEMVs split 2-way over k with 4 accumulators; qbase cached after step 1.
// ---------------------------------------------------------------------------
#define HPS 385
#define DEC_SMEM_BYTES ((128+256+2)*8 + (N*HPS + D*D + D + 2*D + D + 800 + D + D + 104)*4 + 204*4)

__global__ __launch_bounds__(256)
void decode_kernel(const float* __restrict__ x,
                   const float* __restrict__ Wph,
                   const float* __restrict__ Wstep,
                   const float* __restrict__ Wout,
                   float* __restrict__ out) {
    extern __shared__ double dsm[];
    double* sh_qb   = dsm;                  // 128
    double* sh_part = sh_qb + 128;          // 256
    double* sh_ll   = sh_part + 256;        // 2 (ll at [0])
    float* sh_hp   = (float*)(sh_ll + 2);   // N*385
    float* sh_wout = sh_hp + N*HPS;         // 16384
    float* sh_fc   = sh_wout + D*D;         // 128
    float* sh_ctx  = sh_fc + D;             // 256
    float* sh_q    = sh_ctx + 2*D;          // 128
    float* sh_c    = sh_q + D;              // 800
    float* sh_g    = sh_c + 800;            // 128
    float* sh_g2   = sh_g + D;              // 128
    float* sh_lg   = sh_g2 + D;             // 104
    int*   sh_mask = (int*)(sh_lg + 104);   // 100
    int*   sh_pi   = sh_mask + 100;         // 100
    int*   sh_ctrl = sh_pi + 100;           // first, prev

    const double NF = 0.08838834764831843;  // 1/sqrt(D)
    int b = blockIdx.x, tid = threadIdx.x;
    int w = tid >> 5, lane = tid & 31;
    int d128 = tid & 127, half2 = tid >> 7;   // 2-way k split over 128 outputs
    int dh = tid >> 1, parity = tid & 1;      // 2 threads per output

    for (int i = tid; i < N*TD; i += 256) {
        int n = i / TD, j = i - n*TD;
        sh_hp[n*HPS + j] = g_3d[(size_t)b * (N*TD) + i];
    }
    for (int i = tid; i < D*D; i += 256) sh_wout[i] = Wout[i];
    if (tid < D) sh_fc[tid] = g_fc[b*D + tid];
    if (tid < N) sh_mask[tid] = 0;
    if (tid == 0) { sh_ll[0] = 0.0; sh_ctrl[0] = 0; sh_ctrl[1] = 0; }
    __syncthreads();

    for (int s = 0; s < N; s++) {
        // 1. context embeddings
        if (s == 0) {
            sh_ctx[tid] = Wph[tid];
        } else {
            int fa = sh_ctrl[0], pa = sh_ctrl[1];
            if (tid < 128) sh_ctx[tid] = g_h[(size_t)(b*N + fa) * D + tid];
            else           sh_ctx[tid] = g_h[(size_t)(b*N + pa) * D + (tid - 128)];
        }
        __syncthreads();
        // 2. q = fixed + ctx@Wstep  (factored: qbase + prev@W2 for s>=1)
        if (s == 0) {
            double a0=0, a1=0, a2=0, a3=0;
            int k0 = half2 * 128;
#pragma unroll 4
            for (int k = 0; k < 128; k += 4) {
                a0 = fma((double)sh_ctx[k0+k+0], (double)Wstep[(k0+k+0)*D + d128], a0);
                a1 = fma((double)sh_ctx[k0+k+1], (double)Wstep[(k0+k+1)*D + d128], a1);
                a2 = fma((double)sh_ctx[k0+k+2], (double)Wstep[(k0+k+2)*D + d128], a2);
                a3 = fma((double)sh_ctx[k0+k+3], (double)Wstep[(k0+k+3)*D + d128], a3);
            }
            sh_part[tid] = (a0+a1) + (a2+a3);
            __syncthreads();
            if (tid < 128) sh_q[tid] = (float)((double)sh_fc[tid] + sh_part[tid] + sh_part[128+tid]);
        } else {
            if (s == 1) {   // qbase = fixed + first@W1 (first is frozen from here on)
                double a0=0, a1=0, a2=0, a3=0;
                int k0 = half2 * 64;
#pragma unroll 4
                for (int k = 0; k < 64; k += 4) {
                    a0 = fma((double)sh_ctx[k0+k+0], (double)Wstep[(k0+k+0)*D + d128], a0);
                    a1 = fma((double)sh_ctx[k0+k+1], (double)Wstep[(k0+k+1)*D + d128], a1);
                    a2 = fma((double)sh_ctx[k0+k+2], (double)Wstep[(k0+k+2)*D + d128], a2);
                    a3 = fma((double)sh_ctx[k0+k+3], (double)Wstep[(k0+k+3)*D + d128], a3);
                }
                sh_part[tid] = (a0+a1) + (a2+a3);
                __syncthreads();
                if (tid < 128) sh_qb[tid] = (double)sh_fc[tid] + sh_part[tid] + sh_part[128+tid];
                __syncthreads();
            }
            {   // delta = prev@W2
                double a0=0, a1=0, a2=0, a3=0;
                int k0 = half2 * 64;
#pragma unroll 4
                for (int k = 0; k < 64; k += 4) {
                    a0 = fma((double)sh_ctx[128+k0+k+0], (double)Wstep[(128+k0+k+0)*D + d128], a0);
                    a1 = fma((double)sh_ctx[128+k0+k+1], (double)Wstep[(128+k0+k+1)*D + d128], a1);
                    a2 = fma((double)sh_ctx[128+k0+k+2], (double)Wstep[(128+k0+k+2)*D + d128], a2);
                    a3 = fma((double)sh_ctx[128+k0+k+3], (double)Wstep[(128+k0+k+3)*D + d128], a3);
                }
                sh_part[tid] = (a0+a1) + (a2+a3);
                __syncthreads();
                if (tid < 128) sh_q[tid] = (float)(sh_qb[tid] + sh_part[tid] + sh_part[128+tid]);
            }
        }
        __syncthreads();
        // 3. compat [H,N]
        for (int idx = tid; idx < 800; idx += 256) {
            int hh = idx / 100, n = idx - hh*100;
            const float* kp = sh_hp + n*HPS + hh*16;
            const float* qp = sh_q + hh*16;
            double a0 = 0.0, a1 = 0.0;
#pragma unroll
            for (int dd = 0; dd < 16; dd += 2) {
                a0 = fma((double)qp[dd],   (double)kp[dd],   a0);
                a1 = fma((double)qp[dd+1], (double)kp[dd+1], a1);
            }
            sh_c[idx] = sh_mask[n] ? NEGV : (float)((a0+a1) * NF);
        }
        __syncthreads();
        // 4. softmax, one head per warp (8 warps, 8 heads)
        {
            int head = w;
            double mx = -1e30;
            for (int n = lane; n < 100; n += 32) mx = fmax(mx, (double)sh_c[head*100 + n]);
#pragma unroll
            for (int off = 16; off; off >>= 1) mx = fmax(mx, __shfl_xor_sync(0xffffffffu, mx, off));
            double sum = 0.0, ev[4];
#pragma unroll
            for (int j = 0; j < 4; j++) {
                int n = lane + 32*j;
                if (n < 100) { ev[j] = exp((double)sh_c[head*100 + n] - mx); sum += ev[j]; }
                else ev[j] = 0.0;
            }
#pragma unroll
            for (int off = 16; off; off >>= 1) sum += __shfl_xor_sync(0xffffffffu, sum, off);
            double inv = 1.0 / sum;
#pragma unroll
            for (int j = 0; j < 4; j++) {
                int n = lane + 32*j;
                if (n < 100) sh_c[head*100 + n] = (float)(ev[j] * inv);
            }
        }
        __syncthreads();
        // 5. glimpse g[d], d=tid>>1, each thread sums 50 of 100 n's
        {
            int dd = dh, hh = dd >> 4;
            const float* pp = sh_c + hh*100 + parity*50;
            const float* vp = sh_hp + D + dd + (size_t)(parity*50) * HPS;
            double a0 = 0.0, a1 = 0.0;
#pragma unroll 2
            for (int n = 0; n < 50; n += 2) {
                a0 = fma((double)pp[n],   (double)vp[(n)*HPS],   a0);
                a1 = fma((double)pp[n+1], (double)vp[(n+1)*HPS], a1);
            }
            sh_part[tid] = a0 + a1;
        }
        __syncthreads();
        if (tid < 128) sh_g[tid] = (float)(sh_part[2*tid] + sh_part[2*tid+1]);
        __syncthreads();
        // 6. g2 = g @ Wout, 2 threads per output
        {
            int dd = dh, k0 = parity * 64;
            double a0=0, a1=0, a2=0, a3=0;
#pragma unroll 4
            for (int k = 0; k < 64; k += 4) {
                a0 = fma((double)sh_g[k0+k+0], (double)sh_wout[(k0+k+0)*D + dd], a0);
                a1 = fma((double)sh_g[k0+k+1], (double)sh_wout[(k0+k+1)*D + dd], a1);
                a2 = fma((double)sh_g[k0+k+2], (double)sh_wout[(k0+k+2)*D + dd], a2);
                a3 = fma((double)sh_g[k0+k+3], (double)sh_wout[(k0+k+3)*D + dd], a3);
            }
            sh_part[tid] = (a0+a1) + (a2+a3);
        }
        __syncthreads();
        if (tid < 128) sh_g2[tid] = (float)(sh_part[2*tid] + sh_part[2*tid+1]);
        __syncthreads();
        // 7. logits, 2 threads per node
        if (tid < 200) {
            int node = dh, k0 = parity * 64;
            const float* lp = sh_hp + node*HPS + 2*D + k0;
            double a0=0, a1=0, a2=0, a3=0;
#pragma unroll 4
            for (int k = 0; k < 64; k += 4) {
                a0 = fma((double)sh_g2[k0+k+0], (double)lp[k+0], a0);
                a1 = fma((double)sh_g2[k0+k+1], (double)lp[k+1], a1);
                a2 = fma((double)sh_g2[k0+k+2], (double)lp[k+2], a2);
                a3 = fma((double)sh_g2[k0+k+3], (double)lp[k+3], a3);
            }
            sh_part[tid] = (a0+a1) + (a2+a3);
        }
        __syncthreads();
        if (tid < 100) {
            double a = sh_part[2*tid] + sh_part[2*tid+1];
            sh_lg[tid] = sh_mask[tid] ? NEGV : (float)(tanh(a * NF) * CLIPV);
        }
        __syncthreads();
        // 8. argmax (first-max) + logsumexp, warp 0
        if (w == 0) {
            float mx = -1e30f; int mi = N + 1;
            for (int n = lane; n < N; n += 32) {
                float v = sh_lg[n];
                if (v > mx) { mx = v; mi = n; }
            }
#pragma unroll
            for (int off = 16; off; off >>= 1) {
                float om = __shfl_xor_sync(0xffffffffu, mx, off);
                int   oi = __shfl_xor_sync(0xffffffffu, mi, off);
                if (om > mx || (om == mx && oi < mi)) { mx = om; mi = oi; }
            }
            double sum = 0.0;
            for (int n = lane; n < N; n += 32) sum += exp((double)sh_lg[n] - (double)mx);
#pragma unroll
            for (int off = 16; off; off >>= 1) sum += __shfl_xor_sync(0xffffffffu, sum, off);
            if (lane == 0) {
                double lse = (double)mx + log(sum);
                sh_ll[0] += (double)sh_lg[mi] - lse;
                sh_mask[mi] = 1;
                sh_ctrl[1] = mi;
                if (s == 0) sh_ctrl[0] = mi;
                sh_pi[s] = mi;
                out[2*B + b*N + s] = (float)mi;
            }
        }
        __syncthreads();
    }
    // tour cost (closed cycle)
    if (tid < N) {
        int a = sh_pi[tid], c = sh_pi[(tid + 1) % N];
        double dx = (double)x[(b*N + a)*2]     - (double)x[(b*N + c)*2];
        double dy = (double)x[(b*N + a)*2 + 1] - (double)x[(b*N + c)*2 + 1];
        sh_lg[tid] = (float)sqrt(dx*dx + dy*dy);
    }
    __syncthreads();
    if (tid == 0) {
        double cst = 0.0;
        for (int t = 0; t < N; t++) cst += (double)sh_lg[t];
        out[b] = (float)cst;
        out[B + b] = (float)sh_ll[0];
    }
}

// ---------------------------------------------------------------------------
extern "C" void kernel_launch(void* const* d_in, const int* in_sizes, int n_in,
                              void* d_out, int out_size) {
    const float* x        = (const float*)d_in[0];
    const float* init_W   = (const float*)d_in[1];
    const float* init_b   = (const float*)d_in[2];
    const float* qkv_W    = (const float*)d_in[3];
    const float* out_W    = (const float*)d_in[4];
    const float* bn1      = (const float*)d_in[5];
    const float* bn2      = (const float*)d_in[6];
    const float* ff1_W    = (const float*)d_in[7];
    const float* ff1_b    = (const float*)d_in[8];
    const float* ff2_W    = (const float*)d_in[9];
    const float* ff2_b    = (const float*)d_in[10];
    const float* Wph      = (const float*)d_in[11];
    const float* nodes_W  = (const float*)d_in[12];
    const float* fixed_W  = (const float*)d_in[13];
    const float* step_W   = (const float*)d_in[14];
    const float* pout_W   = (const float*)d_in[15];
    float* out = (float*)d_out;

    cudaFuncSetAttribute(decode_kernel, cudaFuncAttributeMaxDynamicSharedMemorySize,
                         DEC_SMEM_BYTES + 128);

    float *p_h, *p_3d, *p_ff, *p_o, *p_s;
    cudaGetSymbolAddress((void**)&p_h,  g_h);
    cudaGetSymbolAddress((void**)&p_3d, g_3d);
    cudaGetSymbolAddress((void**)&p_ff, g_ff);
    cudaGetSymbolAddress((void**)&p_o,  g_o);
    cudaGetSymbolAddress((void**)&p_s,  g_s);

    const int EW = 256;
    int egrid = (M_ROWS * D + EW - 1) / EW;

    init_embed_kernel<<<egrid, EW>>>(x, init_W, init_b);

    for (int l = 0; l < 2; l++) {
        gemm64_kernel<<<dim3(TD/64, M_ROWS/128), 256>>>(
            p_h, qkv_W + (size_t)l*D*TD, nullptr, nullptr, p_3d, M_ROWS, D, TD, 0);
        attn_kernel<<<B*H, 256>>>(p_3d, p_o);
        gemm64_kernel<<<dim3(D/64, M_ROWS/128), 256>>>(
            p_o, out_W + (size_t)l*D*D, nullptr, p_h, p_s, M_ROWS, D, D, 0);
        bn_stats1_kernel<<<128, 256>>>(p_s);
        bn_stats2_kernel<<<1, 128>>>();
        bn_apply_kernel<<<egrid, EW>>>(p_s, bn1 + (size_t)l*2*D, p_h);
        gemm64_kernel<<<dim3(FF/64, M_ROWS/128), 256>>>(
            p_h, ff1_W + (size_t)l*D*FF, ff1_b + (size_t)l*FF, nullptr, p_ff, M_ROWS, D, FF, 1);
        gemm64_kernel<<<dim3(D/64, M_ROWS/128), 256>>>(
            p_ff, ff2_W + (size_t)l*FF*D, ff2_b + (size_t)l*D, p_h, p_s, M_ROWS, FF, D, 0);
        bn_stats1_kernel<<<128, 256>>>(p_s);
        bn_stats2_kernel<<<1, 128>>>();
        bn_apply_kernel<<<egrid, EW>>>(p_s, bn2 + (size_t)l*2*D, p_h);
    }

    gemm64_kernel<<<dim3(TD/64, M_ROWS/128), 256>>>(
        p_h, nodes_W, nullptr, nullptr, p_3d, M_ROWS, D, TD, 0);
    meann_kernel<<<B, D>>>();
    fixedctx_kernel<<<B, D>>>(fixed_W);

    decode_kernel<<<B, 256, DEC_SMEM_BYTES + 128>>>(x, Wph, step_W, pout_W, out);
}

// round 4
// speedup vs baseline: 1.7507x; 1.2175x over previous
#include <cuda_runtime.h>
#include <math.h>
#include <stdint.h>

// Problem constants
#define B 512
#define N 100
#define D 128
#define H 8
#define DK 16
#define FF 512
#define TD 384          // 3*D
#define M_ROWS (B*N)    // 51200
#define NEGV -1e9f
#define CLIPV 10.0

static __device__ float g_h [ (size_t)M_ROWS * D ];     // hidden state
static __device__ float g_3d[ (size_t)M_ROWS * TD ];    // qkv / hp scratch
static __device__ float g_ff[ (size_t)M_ROWS * FF ];    // ff1 output
static __device__ float g_o [ (size_t)M_ROWS * D ];     // attention output
static __device__ float g_s [ (size_t)M_ROWS * D ];     // pre-BN (residual sum)
static __device__ float g_ef[ (size_t)M_ROWS * D ];     // h @ Wstep[0:128]   (first-action table)
static __device__ float g_ed[ (size_t)M_ROWS * D ];     // h @ Wstep[128:256] (prev-action table)
static __device__ double g_part[2][128*128];            // BN partial sums
static __device__ double g_mean[D], g_rstd[D];
static __device__ double g_wphw[D];                     // Wph @ Wstep
static __device__ float g_fc[B*D], g_q0[B*D];           // fixed_ctx, step-0 query

// ---------------------------------------------------------------------------
// h = x @ init_W + init_b
// ---------------------------------------------------------------------------
__global__ void init_embed_kernel(const float* __restrict__ x,
                                  const float* __restrict__ W,
                                  const float* __restrict__ bias) {
    int idx = blockIdx.x * blockDim.x + threadIdx.x;
    if (idx >= M_ROWS * D) return;
    int i = idx >> 7, d = idx & 127;
    double v = (double)x[i*2] * (double)W[d]
             + (double)x[i*2+1] * (double)W[D + d]
             + (double)bias[d];
    g_h[idx] = (float)v;
}

// ---------------------------------------------------------------------------
// Tiled GEMM, fp64 accumulation. BM=128, BN=64, BK=16, 256 threads, 8x4 tile.
// ---------------------------------------------------------------------------
#define AS_STRIDE 129
#define BS_STRIDE 65
__global__ __launch_bounds__(256, 2)
void gemm64_kernel(const float* __restrict__ A, const float* __restrict__ W,
                   const float* __restrict__ bias, const float* __restrict__ res,
                   float* __restrict__ C, int M, int K, int Nc, int relu) {
    __shared__ double As[16 * AS_STRIDE];
    __shared__ double Bs[16 * BS_STRIDE];
    const int tid = threadIdx.x;
    const int tx = tid & 15, ty = tid >> 4;
    const int row0 = blockIdx.y * 128, col0 = blockIdx.x * 64;
    const int ar = tid >> 2, ac = (tid & 3) * 4;
    const int bk = tid >> 4, bc = (tid & 15) * 4;
    double acc[8][4];
#pragma unroll
    for (int i = 0; i < 8; i++)
#pragma unroll
        for (int j = 0; j < 4; j++) acc[i][j] = 0.0;

    for (int kt = 0; kt < K; kt += 16) {
        float4 a0 = *reinterpret_cast<const float4*>(&A[(size_t)(row0+ar)*K + kt + ac]);
        float4 a1 = *reinterpret_cast<const float4*>(&A[(size_t)(row0+ar+64)*K + kt + ac]);
        float4 bv = *reinterpret_cast<const float4*>(&W[(size_t)(kt+bk)*Nc + col0 + bc]);
        As[(ac+0)*AS_STRIDE + ar] = (double)a0.x;
        As[(ac+1)*AS_STRIDE + ar] = (double)a0.y;
        As[(ac+2)*AS_STRIDE + ar] = (double)a0.z;
        As[(ac+3)*AS_STRIDE + ar] = (double)a0.w;
        As[(ac+0)*AS_STRIDE + ar+64] = (double)a1.x;
        As[(ac+1)*AS_STRIDE + ar+64] = (double)a1.y;
        As[(ac+2)*AS_STRIDE + ar+64] = (double)a1.z;
        As[(ac+3)*AS_STRIDE + ar+64] = (double)a1.w;
        Bs[bk*BS_STRIDE + bc+0] = (double)bv.x;
        Bs[bk*BS_STRIDE + bc+1] = (double)bv.y;
        Bs[bk*BS_STRIDE + bc+2] = (double)bv.z;
        Bs[bk*BS_STRIDE + bc+3] = (double)bv.w;
        __syncthreads();
#pragma unroll
        for (int k = 0; k < 16; k++) {
            double a[8], bb[4];
#pragma unroll
            for (int i = 0; i < 8; i++) a[i] = As[k*AS_STRIDE + ty + 16*i];
#pragma unroll
            for (int j = 0; j < 4; j++) bb[j] = Bs[k*BS_STRIDE + tx + 16*j];
#pragma unroll
            for (int i = 0; i < 8; i++)
#pragma unroll
                for (int j = 0; j < 4; j++) acc[i][j] = fma(a[i], bb[j], acc[i][j]);
        }
        __syncthreads();
    }
#pragma unroll
    for (int i = 0; i < 8; i++) {
        int r = row0 + ty + 16*i;
#pragma unroll
        for (int j = 0; j < 4; j++) {
            int c = col0 + tx + 16*j;
            double v = acc[i][j];
            if (bias) v += (double)bias[c];
            if (res)  v += (double)res[(size_t)r*Nc + c];
            if (relu) v = v > 0.0 ? v : 0.0;
            C[(size_t)r*Nc + c] = (float)v;
        }
    }
}

// ---------------------------------------------------------------------------
// Fused MHA: qkv [B,N,3D] -> o [B,N,D]. One block per (b,h).
// ---------------------------------------------------------------------------
__global__ __launch_bounds__(256)
void attn_kernel(const float* __restrict__ qkv, float* __restrict__ o) {
    int bh = blockIdx.x;
    int b = bh >> 3, hh = bh & 7;
    __shared__ float ksh[100*17];
    __shared__ float vsh[100*17];
    __shared__ float psh[8][100];
    int tid = threadIdx.x;
    for (int i = tid; i < 1600; i += 256) {
        int m = i >> 4, d = i & 15;
        const float* base = qkv + (size_t)(b*N + m) * TD + hh*16 + d;
        ksh[m*17 + d] = base[D];
        vsh[m*17 + d] = base[2*D];
    }
    __syncthreads();
    int w = tid >> 5, lane = tid & 31;
    for (int n = w; n < N; n += 8) {
        const float* qp = qkv + (size_t)(b*N + n) * TD + hh*16;
        double qreg[16];
#pragma unroll
        for (int d = 0; d < 16; d++) qreg[d] = (double)qp[d];
        double s[4];
        double mx = -1e30;
#pragma unroll
        for (int j = 0; j < 4; j++) {
            int m = lane + 32*j;
            if (m < N) {
                double a0 = 0.0, a1 = 0.0;
#pragma unroll
                for (int d = 0; d < 16; d += 2) {
                    a0 = fma(qreg[d],   (double)ksh[m*17 + d],   a0);
                    a1 = fma(qreg[d+1], (double)ksh[m*17 + d+1], a1);
                }
                s[j] = (a0 + a1) * 0.25;
                mx = fmax(mx, s[j]);
            } else s[j] = -1e30;
        }
#pragma unroll
        for (int off = 16; off; off >>= 1) mx = fmax(mx, __shfl_xor_sync(0xffffffffu, mx, off));
        double sum = 0.0;
#pragma unroll
        for (int j = 0; j < 4; j++) {
            int m = lane + 32*j;
            if (m < N) { s[j] = exp(s[j] - mx); sum += s[j]; }
        }
#pragma unroll
        for (int off = 16; off; off >>= 1) sum += __shfl_xor_sync(0xffffffffu, sum, off);
        double inv = 1.0 / sum;
#pragma unroll
        for (int j = 0; j < 4; j++) {
            int m = lane + 32*j;
            if (m < N) psh[w][m] = (float)(s[j] * inv);
        }
        __syncwarp();
        if (lane < 16) {
            double a0 = 0.0, a1 = 0.0, a2 = 0.0, a3 = 0.0;
            for (int m = 0; m < 100; m += 4) {
                a0 = fma((double)psh[w][m],   (double)vsh[(m)*17 + lane],   a0);
                a1 = fma((double)psh[w][m+1], (double)vsh[(m+1)*17 + lane], a1);
                a2 = fma((double)psh[w][m+2], (double)vsh[(m+2)*17 + lane], a2);
                a3 = fma((double)psh[w][m+3], (double)vsh[(m+3)*17 + lane], a3);
            }
            o[(size_t)(b*N + n) * D + hh*16 + lane] = (float)((a0+a1)+(a2+a3));
        }
        __syncwarp();
    }
}

// ---------------------------------------------------------------------------
// BatchNorm, two-stage deterministic reduction (double).
// ---------------------------------------------------------------------------
__global__ void bn_stats1_kernel(const float* __restrict__ s) {
    __shared__ double ssum[256], ssq[256];
    int p = blockIdx.x, tid = threadIdx.x;
    int c = tid & 127, roff = tid >> 7;
    double a = 0.0, q = 0.0;
    size_t base = (size_t)p * 400 * D;
    for (int r = roff; r < 400; r += 2) {
        double v = (double)s[base + (size_t)r * D + c];
        a += v; q = fma(v, v, q);
    }
    ssum[tid] = a; ssq[tid] = q;
    __syncthreads();
    if (tid < 128) {
        g_part[0][p*128 + tid] = ssum[tid] + ssum[tid+128];
        g_part[1][p*128 + tid] = ssq[tid]  + ssq[tid+128];
    }
}
__global__ void bn_stats2_kernel() {
    int c = threadIdx.x;
    double a = 0.0, q = 0.0;
    for (int p = 0; p < 128; p++) { a += g_part[0][p*128 + c]; q += g_part[1][p*128 + c]; }
    double mean = a * (1.0 / (double)M_ROWS);
    double var  = q * (1.0 / (double)M_ROWS) - mean*mean;
    g_mean[c] = mean;
    g_rstd[c] = 1.0 / sqrt(var + 1e-5);
}
__global__ void bn_apply_kernel(const float* __restrict__ s, const float* __restrict__ gb,
                                float* __restrict__ h) {
    int idx = blockIdx.x * blockDim.x + threadIdx.x;
    if (idx >= M_ROWS * D) return;
    int d = idx & 127;
    double v = (double)gb[d] * ((double)s[idx] - g_mean[d]) * g_rstd[d] + (double)gb[D + d];
    h[idx] = (float)v;
}

// ---------------------------------------------------------------------------
// wphw[d] = Wph @ Wstep (column d)  -- one block, 128 threads
// ---------------------------------------------------------------------------
__global__ void wphw_kernel(const float* __restrict__ Wph, const float* __restrict__ Wstep) {
    int d = threadIdx.x;
    double a0 = 0.0, a1 = 0.0;
    for (int k = 0; k < 2*D; k += 2) {
        a0 = fma((double)Wph[k],   (double)Wstep[(k)*D + d],   a0);
        a1 = fma((double)Wph[k+1], (double)Wstep[(k+1)*D + d], a1);
    }
    g_wphw[d] = a0 + a1;
}

// ---------------------------------------------------------------------------
// Per-batch: hm = mean_n(h); fc = hm @ Wf; q0 = fc + wphw
// ---------------------------------------------------------------------------
__global__ void meanfix_kernel(const float* __restrict__ Wf) {
    __shared__ float sh[D];
    int b = blockIdx.x, d = threadIdx.x;
    double a = 0.0;
    for (int n = 0; n < N; n++) a += (double)g_h[(size_t)(b*N + n) * D + d];
    sh[d] = (float)(a * (1.0 / (double)N));
    __syncthreads();
    double fc = 0.0;
    for (int k = 0; k < D; k++) fc = fma((double)sh[k], (double)Wf[k*D + d], fc);
    g_fc[b*D + d] = (float)fc;
    g_q0[b*D + d] = (float)(fc + g_wphw[d]);
}

// ---------------------------------------------------------------------------
// Persistent greedy decode. 512 threads/block, 1 block per batch element.
// q is a table lookup (Efirst/Edelta precomputed); GEMVs 4-way k-split.
// ---------------------------------------------------------------------------
#define HPS 385
#define DEC_SMEM_BYTES (16 + (38500 + 16384 + 128 + 128 + 800 + 128 + 128 + 512 + 100)*4 + 202*4)

__global__ __launch_bounds__(512)
void decode_kernel(const float* __restrict__ x,
                   const float* __restrict__ Wout,
                   float* __restrict__ out) {
    extern __shared__ double dsm[];
    double* sh_ll  = dsm;                   // [1]
    float* sh_hp   = (float*)(dsm + 2);     // 100*385
    float* sh_wout = sh_hp + N*HPS;         // 16384
    float* sh_q    = sh_wout + D*D;         // 128
    float* sh_qb   = sh_q + D;              // 128
    float* sh_c    = sh_qb + D;             // 800
    float* sh_g    = sh_c + 800;            // 128
    float* sh_g2   = sh_g + D;              // 128
    float* sh_part = sh_g2 + D;             // 512
    float* sh_lg   = sh_part + 512;         // 100
    int*   sh_mask = (int*)(sh_lg + 100);   // 100
    int*   sh_pi   = sh_mask + 100;         // 100
    int*   sh_ctrl = sh_pi + 100;           // first, prev

    const double NF = 0.08838834764831843;  // 1/sqrt(D)
    int b = blockIdx.x, tid = threadIdx.x;
    int w = tid >> 5, lane = tid & 31;
    int dd = tid & 127, part = tid >> 7;    // 4-way k/n split over 128 outputs

    for (int i = tid; i < N*TD; i += 512) {
        int n = i / TD, j = i - n*TD;
        sh_hp[n*HPS + j] = g_3d[(size_t)b * (N*TD) + i];
    }
    for (int i = tid; i < D*D; i += 512) sh_wout[i] = Wout[i];
    if (tid < N) sh_mask[tid] = 0;
    if (tid == 0) { sh_ll[0] = 0.0; sh_ctrl[0] = 0; sh_ctrl[1] = 0; }
    __syncthreads();

    for (int s = 0; s < N; s++) {
        // 1. q from precomputed tables (no GEMV)
        if (tid < 128) {
            if (s == 0) {
                sh_q[tid] = g_q0[b*D + tid];
            } else {
                float qb;
                if (s == 1) {
                    qb = g_fc[b*D + tid] + g_ef[(size_t)(b*N + sh_ctrl[0]) * D + tid];
                    sh_qb[tid] = qb;
                } else qb = sh_qb[tid];
                sh_q[tid] = qb + g_ed[(size_t)(b*N + sh_ctrl[1]) * D + tid];
            }
        }
        __syncthreads();
        // 2. compat [H,N]
        for (int idx = tid; idx < 800; idx += 512) {
            int hh = idx / 100, n = idx - hh*100;
            const float* kp = sh_hp + n*HPS + hh*16;
            const float* qp = sh_q + hh*16;
            double a0 = 0.0, a1 = 0.0;
#pragma unroll
            for (int d2 = 0; d2 < 16; d2 += 2) {
                a0 = fma((double)qp[d2],   (double)kp[d2],   a0);
                a1 = fma((double)qp[d2+1], (double)kp[d2+1], a1);
            }
            sh_c[idx] = sh_mask[n] ? NEGV : (float)((a0+a1) * NF);
        }
        __syncthreads();
        // 3. softmax, warps 0-7 (one head each)
        if (w < 8) {
            int head = w;
            double mx = -1e30;
            for (int n = lane; n < 100; n += 32) mx = fmax(mx, (double)sh_c[head*100 + n]);
#pragma unroll
            for (int off = 16; off; off >>= 1) mx = fmax(mx, __shfl_xor_sync(0xffffffffu, mx, off));
            double sum = 0.0, ev[4];
#pragma unroll
            for (int j = 0; j < 4; j++) {
                int n = lane + 32*j;
                if (n < 100) { ev[j] = exp((double)sh_c[head*100 + n] - mx); sum += ev[j]; }
                else ev[j] = 0.0;
            }
#pragma unroll
            for (int off = 16; off; off >>= 1) sum += __shfl_xor_sync(0xffffffffu, sum, off);
            double inv = 1.0 / sum;
#pragma unroll
            for (int j = 0; j < 4; j++) {
                int n = lane + 32*j;
                if (n < 100) sh_c[head*100 + n] = (float)(ev[j] * inv);
            }
        }
        __syncthreads();
        // 4. glimpse partials: thread (dd, part) sums n in [part*25, part*25+25)
        {
            int hh = dd >> 4;
            const float* pp = sh_c + hh*100 + part*25;
            const float* vp = sh_hp + (size_t)(part*25) * HPS + D + dd;
            double a0 = 0.0, a1 = 0.0;
#pragma unroll 4
            for (int n = 0; n < 24; n += 2) {
                a0 = fma((double)pp[n],   (double)vp[(n)*HPS],   a0);
                a1 = fma((double)pp[n+1], (double)vp[(n+1)*HPS], a1);
            }
            a0 = fma((double)pp[24], (double)vp[24*HPS], a0);
            sh_part[tid] = (float)(a0 + a1);
        }
        __syncthreads();
        if (tid < 128) sh_g[tid] = sh_part[tid] + sh_part[tid+128] + sh_part[tid+256] + sh_part[tid+384];
        __syncthreads();
        // 5. g2 partials: thread (dd, part) over k in [part*32, +32)
        {
            int k0 = part * 32;
            double a0=0, a1=0;
#pragma unroll 4
            for (int k = 0; k < 32; k += 2) {
                a0 = fma((double)sh_g[k0+k],   (double)sh_wout[(k0+k)*D + dd],   a0);
                a1 = fma((double)sh_g[k0+k+1], (double)sh_wout[(k0+k+1)*D + dd], a1);
            }
            sh_part[tid] = (float)(a0 + a1);
        }
        __syncthreads();
        if (tid < 128) sh_g2[tid] = sh_part[tid] + sh_part[tid+128] + sh_part[tid+256] + sh_part[tid+384];
        __syncthreads();
        // 6. logits partials: node = dd (if < 100), k range part*32
        if (dd < 100) {
            int k0 = part * 32;
            const float* lp = sh_hp + dd*HPS + 2*D + k0;
            double a0=0, a1=0;
#pragma unroll 4
            for (int k = 0; k < 32; k += 2) {
                a0 = fma((double)sh_g2[k0+k],   (double)lp[k],   a0);
                a1 = fma((double)sh_g2[k0+k+1], (double)lp[k+1], a1);
            }
            sh_part[tid] = (float)(a0 + a1);
        }
        __syncthreads();
        if (tid < 100) {
            double a = (double)sh_part[tid] + (double)sh_part[tid+128]
                     + (double)sh_part[tid+256] + (double)sh_part[tid+384];
            sh_lg[tid] = sh_mask[tid] ? NEGV : (float)(tanh(a * NF) * CLIPV);
        }
        __syncthreads();
        // 7. argmax (first-max) + logsumexp, warp 0
        if (w == 0) {
            float mx = -1e30f; int mi = N + 1;
            for (int n = lane; n < N; n += 32) {
                float v = sh_lg[n];
                if (v > mx) { mx = v; mi = n; }
            }
#pragma unroll
            for (int off = 16; off; off >>= 1) {
                float om = __shfl_xor_sync(0xffffffffu, mx, off);
                int   oi = __shfl_xor_sync(0xffffffffu, mi, off);
                if (om > mx || (om == mx && oi < mi)) { mx = om; mi = oi; }
            }
            double sum = 0.0;
            for (int n = lane; n < N; n += 32) sum += exp((double)sh_lg[n] - (double)mx);
#pragma unroll
            for (int off = 16; off; off >>= 1) sum += __shfl_xor_sync(0xffffffffu, sum, off);
            if (lane == 0) {
                double lse = (double)mx + log(sum);
                sh_ll[0] += (double)sh_lg[mi] - lse;
                sh_mask[mi] = 1;
                sh_ctrl[1] = mi;
                if (s == 0) sh_ctrl[0] = mi;
                sh_pi[s] = mi;
                out[2*B + b*N + s] = (float)mi;
            }
        }
        __syncthreads();
    }
    // tour cost (closed cycle)
    if (tid < N) {
        int a = sh_pi[tid], c = sh_pi[(tid + 1) % N];
        double dx = (double)x[(b*N + a)*2]     - (double)x[(b*N + c)*2];
        double dy = (double)x[(b*N + a)*2 + 1] - (double)x[(b*N + c)*2 + 1];
        sh_lg[tid] = (float)sqrt(dx*dx + dy*dy);
    }
    __syncthreads();
    if (tid == 0) {
        double cst = 0.0;
        for (int t = 0; t < N; t++) cst += (double)sh_lg[t];
        out[b] = (float)cst;
        out[B + b] = (float)sh_ll[0];
    }
}

// ---------------------------------------------------------------------------
extern "C" void kernel_launch(void* const* d_in, const int* in_sizes, int n_in,
                              void* d_out, int out_size) {
    const float* x        = (const float*)d_in[0];
    const float* init_W   = (const float*)d_in[1];
    const float* init_b   = (const float*)d_in[2];
    const float* qkv_W    = (const float*)d_in[3];
    const float* out_W    = (const float*)d_in[4];
    const float* bn1      = (const float*)d_in[5];
    const float* bn2      = (const float*)d_in[6];
    const float* ff1_W    = (const float*)d_in[7];
    const float* ff1_b    = (const float*)d_in[8];
    const float* ff2_W    = (const float*)d_in[9];
    const float* ff2_b    = (const float*)d_in[10];
    const float* Wph      = (const float*)d_in[11];
    const float* nodes_W  = (const float*)d_in[12];
    const float* fixed_W  = (const float*)d_in[13];
    const float* step_W   = (const float*)d_in[14];
    const float* pout_W   = (const float*)d_in[15];
    float* out = (float*)d_out;

    cudaFuncSetAttribute(decode_kernel, cudaFuncAttributeMaxDynamicSharedMemorySize,
                         DEC_SMEM_BYTES + 128);

    float *p_h, *p_3d, *p_ff, *p_o, *p_s, *p_ef, *p_ed;
    cudaGetSymbolAddress((void**)&p_h,  g_h);
    cudaGetSymbolAddress((void**)&p_3d, g_3d);
    cudaGetSymbolAddress((void**)&p_ff, g_ff);
    cudaGetSymbolAddress((void**)&p_o,  g_o);
    cudaGetSymbolAddress((void**)&p_s,  g_s);
    cudaGetSymbolAddress((void**)&p_ef, g_ef);
    cudaGetSymbolAddress((void**)&p_ed, g_ed);

    const int EW = 256;
    int egrid = (M_ROWS * D + EW - 1) / EW;

    init_embed_kernel<<<egrid, EW>>>(x, init_W, init_b);
    wphw_kernel<<<1, 128>>>(Wph, step_W);

    for (int l = 0; l < 2; l++) {
        gemm64_kernel<<<dim3(TD/64, M_ROWS/128), 256>>>(
            p_h, qkv_W + (size_t)l*D*TD, nullptr, nullptr, p_3d, M_ROWS, D, TD, 0);
        attn_kernel<<<B*H, 256>>>(p_3d, p_o);
        gemm64_kernel<<<dim3(D/64, M_ROWS/128), 256>>>(
            p_o, out_W + (size_t)l*D*D, nullptr, p_h, p_s, M_ROWS, D, D, 0);
        bn_stats1_kernel<<<128, 256>>>(p_s);
        bn_stats2_kernel<<<1, 128>>>();
        bn_apply_kernel<<<egrid, EW>>>(p_s, bn1 + (size_t)l*2*D, p_h);
        gemm64_kernel<<<dim3(FF/64, M_ROWS/128), 256>>>(
            p_h, ff1_W + (size_t)l*D*FF, ff1_b + (size_t)l*FF, nullptr, p_ff, M_ROWS, D, FF, 1);
        gemm64_kernel<<<dim3(D/64, M_ROWS/128), 256>>>(
            p_ff, ff2_W + (size_t)l*FF*D, ff2_b + (size_t)l*D, p_h, p_s, M_ROWS, FF, D, 0);
        bn_stats1_kernel<<<128, 256>>>(p_s);
        bn_stats2_kernel<<<1, 128>>>();
        bn_apply_kernel<<<egrid, EW>>>(p_s, bn2 + (size_t)l*2*D, p_h);
    }

    // decoder precompute: nodes projection + q lookup tables + fixed ctx
    gemm64_kernel<<<dim3(TD/64, M_ROWS/128), 256>>>(
        p_h, nodes_W, nullptr, nullptr, p_3d, M_ROWS, D, TD, 0);
    gemm64_kernel<<<dim3(D/64, M_ROWS/128), 256>>>(
        p_h, step_W, nullptr, nullptr, p_ef, M_ROWS, D, D, 0);
    gemm64_kernel<<<dim3(D/64, M_ROWS/128), 256>>>(
        p_h, step_W + (size_t)D*D, nullptr, nullptr, p_ed, M_ROWS, D, D, 0);
    meanfix_kernel<<<B, D>>>(fixed_W);

    decode_kernel<<<B, 512, DEC_SMEM_BYTES + 128>>>(x, pout_W, out);
}

// round 6
// speedup vs baseline: 2.2163x; 1.2660x over previous
#include <cuda_runtime.h>
#include <math.h>
#include <stdint.h>

// Problem constants
#define B 512
#define N 100
#define D 128
#define H 8
#define DK 16
#define FF 512
#define TD 384          // 3*D
#define M_ROWS (B*N)    // 51200
#define NEGV -1e9f
#define CLIPV 10.0

static __device__ float g_h [ (size_t)M_ROWS * D ];     // hidden state
static __device__ float g_3d[ (size_t)M_ROWS * TD ];    // qkv / hp scratch
static __device__ float g_ff[ (size_t)M_ROWS * FF ];    // ff1 output
static __device__ float g_o [ (size_t)M_ROWS * D ];     // attention output
static __device__ float g_s [ (size_t)M_ROWS * D ];     // pre-BN (residual sum)
static __device__ float g_ef[ (size_t)M_ROWS * D ];     // h @ Wstep[0:128]
static __device__ float g_ed[ (size_t)M_ROWS * D ];     // h @ Wstep[128:256]
static __device__ double g_part[2][128*128];            // BN partial sums
static __device__ double g_mean[D], g_rstd[D];
static __device__ double g_wphw[D];                     // Wph @ Wstep
static __device__ float g_fc[B*D], g_q0[B*D];           // fixed_ctx, step-0 query

// ---------------------------------------------------------------------------
// h = x @ init_W + init_b
// ---------------------------------------------------------------------------
__global__ void init_embed_kernel(const float* __restrict__ x,
                                  const float* __restrict__ W,
                                  const float* __restrict__ bias) {
    int idx = blockIdx.x * blockDim.x + threadIdx.x;
    if (idx >= M_ROWS * D) return;
    int i = idx >> 7, d = idx & 127;
    double v = (double)x[i*2] * (double)W[d]
             + (double)x[i*2+1] * (double)W[D + d]
             + (double)bias[d];
    g_h[idx] = (float)v;
}

// ---------------------------------------------------------------------------
// fp32 tiled GEMM: C[M,Nc] = A[M,K] @ W[K,Nc] (+bias)(+res)(relu)
// BM=BN=128, BK=16, 256 threads, 8x8 per thread (4+4 split). Pure FFMA.
// ---------------------------------------------------------------------------
__global__ __launch_bounds__(256, 2)
void gemm32_kernel(const float* __restrict__ A, const float* __restrict__ W,
                   const float* __restrict__ bias, const float* __restrict__ res,
                   float* __restrict__ C, int M, int K, int Nc, int relu) {
    __shared__ float As[16][132];
    __shared__ float Bs[16][132];
    const int tid = threadIdx.x;
    const int tx = tid & 15, ty = tid >> 4;
    const int row0 = blockIdx.y * 128, col0 = blockIdx.x * 128;
    float acc[8][8];
#pragma unroll
    for (int i = 0; i < 8; i++)
#pragma unroll
        for (int j = 0; j < 8; j++) acc[i][j] = 0.f;

    for (int kt = 0; kt < K; kt += 16) {
#pragma unroll
        for (int p = 0; p < 2; p++) {
            int idx = tid + p*256;
            int r = idx >> 2, kc = (idx & 3) * 4;
            float4 v = *reinterpret_cast<const float4*>(&A[(size_t)(row0+r)*K + kt + kc]);
            As[kc+0][r] = v.x; As[kc+1][r] = v.y; As[kc+2][r] = v.z; As[kc+3][r] = v.w;
        }
#pragma unroll
        for (int p = 0; p < 2; p++) {
            int idx = tid + p*256;
            int kr = idx >> 5, c = (idx & 31) * 4;
            float4 v = *reinterpret_cast<const float4*>(&W[(size_t)(kt+kr)*Nc + col0 + c]);
            *reinterpret_cast<float4*>(&Bs[kr][c]) = v;
        }
        __syncthreads();
#pragma unroll
        for (int k = 0; k < 16; k++) {
            float a[8], bb[8];
            float4 a0 = *reinterpret_cast<const float4*>(&As[k][ty*4]);
            float4 a1 = *reinterpret_cast<const float4*>(&As[k][64 + ty*4]);
            float4 b0 = *reinterpret_cast<const float4*>(&Bs[k][tx*4]);
            float4 b1 = *reinterpret_cast<const float4*>(&Bs[k][64 + tx*4]);
            a[0]=a0.x;a[1]=a0.y;a[2]=a0.z;a[3]=a0.w;a[4]=a1.x;a[5]=a1.y;a[6]=a1.z;a[7]=a1.w;
            bb[0]=b0.x;bb[1]=b0.y;bb[2]=b0.z;bb[3]=b0.w;bb[4]=b1.x;bb[5]=b1.y;bb[6]=b1.z;bb[7]=b1.w;
#pragma unroll
            for (int i = 0; i < 8; i++)
#pragma unroll
                for (int j = 0; j < 8; j++) acc[i][j] = fmaf(a[i], bb[j], acc[i][j]);
        }
        __syncthreads();
    }
#pragma unroll
    for (int i = 0; i < 8; i++) {
        int r = row0 + ty*4 + (i < 4 ? i : 60 + i);
#pragma unroll
        for (int j = 0; j < 8; j++) {
            int c = col0 + tx*4 + (j < 4 ? j : 60 + j);
            float v = acc[i][j];
            if (bias) v += bias[c];
            if (res)  v += res[(size_t)r*Nc + c];
            if (relu) v = fmaxf(v, 0.f);
            C[(size_t)r*Nc + c] = v;
        }
    }
}

// ---------------------------------------------------------------------------
// Fused MHA v2: one block per (b,h). Dynamic smem (60.4 KB).
//   1. scores[100][100] fully parallel (fp64 dot, fp32 store)
//   2. per-row softmax (warp per row, double exp)
//   3. O = P @ V over 1600 (n,dk) outputs (fp64 accum)
// ---------------------------------------------------------------------------
#define ATTN_SMEM_BYTES ((3*1700 + 10000) * 4)
__global__ __launch_bounds__(256)
void attn_kernel(const float* __restrict__ qkv, float* __restrict__ o) {
    extern __shared__ float asm_[];
    float* qsh = asm_;            // 100*17
    float* ksh = qsh + 1700;      // 100*17
    float* vsh = ksh + 1700;      // 100*17
    float* psh = vsh + 1700;      // 100*100
    int bh = blockIdx.x;
    int b = bh >> 3, hh = bh & 7;
    int tid = threadIdx.x;
    for (int i = tid; i < 1600; i += 256) {
        int m = i >> 4, d = i & 15;
        const float* base = qkv + (size_t)(b*N + m) * TD + hh*16 + d;
        qsh[m*17 + d] = base[0];
        ksh[m*17 + d] = base[D];
        vsh[m*17 + d] = base[2*D];
    }
    __syncthreads();
    // phase 1: scores
    for (int idx = tid; idx < 10000; idx += 256) {
        int n = idx / 100, m = idx - n*100;
        const float* qp = qsh + n*17;
        const float* kp = ksh + m*17;
        double a0 = 0.0, a1 = 0.0;
#pragma unroll
        for (int d = 0; d < 16; d += 2) {
            a0 = fma((double)qp[d],   (double)kp[d],   a0);
            a1 = fma((double)qp[d+1], (double)kp[d+1], a1);
        }
        psh[idx] = (float)((a0 + a1) * 0.25);
    }
    __syncthreads();
    // phase 2: softmax per row (warp per row)
    int w = tid >> 5, lane = tid & 31;
    for (int n = w; n < 100; n += 8) {
        float* row = psh + n*100;
        double mx = -1e30;
        double sv[4];
#pragma unroll
        for (int j = 0; j < 4; j++) {
            int m = lane + 32*j;
            sv[j] = (m < 100) ? (double)row[m] : -1e30;
            mx = fmax(mx, sv[j]);
        }
#pragma unroll
        for (int off = 16; off; off >>= 1) mx = fmax(mx, __shfl_xor_sync(0xffffffffu, mx, off));
        double sum = 0.0;
#pragma unroll
        for (int j = 0; j < 4; j++) {
            int m = lane + 32*j;
            if (m < 100) { sv[j] = exp(sv[j] - mx); sum += sv[j]; }
        }
#pragma unroll
        for (int off = 16; off; off >>= 1) sum += __shfl_xor_sync(0xffffffffu, sum, off);
        double inv = 1.0 / sum;
#pragma unroll
        for (int j = 0; j < 4; j++) {
            int m = lane + 32*j;
            if (m < 100) row[m] = (float)(sv[j] * inv);
        }
    }
    __syncthreads();
    // phase 3: O = P @ V
    for (int idx = tid; idx < 1600; idx += 256) {
        int n = idx >> 4, dk = idx & 15;
        const float* pp = psh + n*100;
        const float* vp = vsh + dk;
        double a0 = 0.0, a1 = 0.0;
#pragma unroll 2
        for (int m = 0; m < 100; m += 2) {
            a0 = fma((double)pp[m],   (double)vp[(m)*17],   a0);
            a1 = fma((double)pp[m+1], (double)vp[(m+1)*17], a1);
        }
        o[(size_t)(b*N + n) * D + hh*16 + dk] = (float)(a0 + a1);
    }
}

// ---------------------------------------------------------------------------
// BatchNorm, two-stage deterministic reduction (double).
// ---------------------------------------------------------------------------
__global__ void bn_stats1_kernel(const float* __restrict__ s) {
    __shared__ double ssum[256], ssq[256];
    int p = blockIdx.x, tid = threadIdx.x;
    int c = tid & 127, roff = tid >> 7;
    double a = 0.0, q = 0.0;
    size_t base = (size_t)p * 400 * D;
    for (int r = roff; r < 400; r += 2) {
        double v = (double)s[base + (size_t)r * D + c];
        a += v; q = fma(v, v, q);
    }
    ssum[tid] = a; ssq[tid] = q;
    __syncthreads();
    if (tid < 128) {
        g_part[0][p*128 + tid] = ssum[tid] + ssum[tid+128];
        g_part[1][p*128 + tid] = ssq[tid]  + ssq[tid+128];
    }
}
__global__ void bn_stats2_kernel() {
    int c = threadIdx.x;
    double a = 0.0, q = 0.0;
    for (int p = 0; p < 128; p++) { a += g_part[0][p*128 + c]; q += g_part[1][p*128 + c]; }
    double mean = a * (1.0 / (double)M_ROWS);
    double var  = q * (1.0 / (double)M_ROWS) - mean*mean;
    g_mean[c] = mean;
    g_rstd[c] = 1.0 / sqrt(var + 1e-5);
}
__global__ void bn_apply_kernel(const float* __restrict__ s, const float* __restrict__ gb,
                                float* __restrict__ h) {
    int idx = blockIdx.x * blockDim.x + threadIdx.x;
    if (idx >= M_ROWS * D) return;
    int d = idx & 127;
    double v = (double)gb[d] * ((double)s[idx] - g_mean[d]) * g_rstd[d] + (double)gb[D + d];
    h[idx] = (float)v;
}

// ---------------------------------------------------------------------------
// wphw[d] = Wph @ Wstep (column d)
// ---------------------------------------------------------------------------
__global__ void wphw_kernel(const float* __restrict__ Wph, const float* __restrict__ Wstep) {
    int d = threadIdx.x;
    double a0 = 0.0, a1 = 0.0;
    for (int k = 0; k < 2*D; k += 2) {
        a0 = fma((double)Wph[k],   (double)Wstep[(k)*D + d],   a0);
        a1 = fma((double)Wph[k+1], (double)Wstep[(k+1)*D + d], a1);
    }
    g_wphw[d] = a0 + a1;
}

// ---------------------------------------------------------------------------
// Per-batch: hm = mean_n(h); fc = hm @ Wf; q0 = fc + wphw
// ---------------------------------------------------------------------------
__global__ void meanfix_kernel(const float* __restrict__ Wf) {
    __shared__ float sh[D];
    int b = blockIdx.x, d = threadIdx.x;
    double a = 0.0;
    for (int n = 0; n < N; n++) a += (double)g_h[(size_t)(b*N + n) * D + d];
    sh[d] = (float)(a * (1.0 / (double)N));
    __syncthreads();
    double fc = 0.0;
    for (int k = 0; k < D; k++) fc = fma((double)sh[k], (double)Wf[k*D + d], fc);
    g_fc[b*D + d] = (float)fc;
    g_q0[b*D + d] = (float)(fc + g_wphw[d]);
}

// ---------------------------------------------------------------------------
// Persistent greedy decode. 512 threads/block, 1 block per batch element.
// ---------------------------------------------------------------------------
#define HPS 385
#define DEC_SMEM_BYTES (16 + (38500 + 16384 + 128 + 128 + 800 + 128 + 128 + 512 + 100)*4 + 202*4)

__global__ __launch_bounds__(512)
void decode_kernel(const float* __restrict__ x,
                   const float* __restrict__ Wout,
                   float* __restrict__ out) {
    extern __shared__ double dsm[];
    double* sh_ll  = dsm;                   // [1]
    float* sh_hp   = (float*)(dsm + 2);     // 100*385
    float* sh_wout = sh_hp + N*HPS;         // 16384
    float* sh_q    = sh_wout + D*D;         // 128
    float* sh_qb   = sh_q + D;              // 128
    float* sh_c    = sh_qb + D;             // 800
    float* sh_g    = sh_c + 800;            // 128
    float* sh_g2   = sh_g + D;              // 128
    float* sh_part = sh_g2 + D;             // 512
    float* sh_lg   = sh_part + 512;         // 100
    int*   sh_mask = (int*)(sh_lg + 100);   // 100
    int*   sh_pi   = sh_mask + 100;         // 100
    int*   sh_ctrl = sh_pi + 100;           // first, prev

    const double NF = 0.08838834764831843;  // 1/sqrt(D)
    int b = blockIdx.x, tid = threadIdx.x;
    int w = tid >> 5, lane = tid & 31;
    int dd = tid & 127, part = tid >> 7;

    for (int i = tid; i < N*TD; i += 512) {
        int n = i / TD, j = i - n*TD;
        sh_hp[n*HPS + j] = g_3d[(size_t)b * (N*TD) + i];
    }
    for (int i = tid; i < D*D; i += 512) sh_wout[i] = Wout[i];
    if (tid < N) sh_mask[tid] = 0;
    if (tid == 0) { sh_ll[0] = 0.0; sh_ctrl[0] = 0; sh_ctrl[1] = 0; }
    __syncthreads();

    for (int s = 0; s < N; s++) {
        // 1. q from precomputed tables
        if (tid < 128) {
            if (s == 0) {
                sh_q[tid] = g_q0[b*D + tid];
            } else {
                float qb;
                if (s == 1) {
                    qb = g_fc[b*D + tid] + g_ef[(size_t)(b*N + sh_ctrl[0]) * D + tid];
                    sh_qb[tid] = qb;
                } else qb = sh_qb[tid];
                sh_q[tid] = qb + g_ed[(size_t)(b*N + sh_ctrl[1]) * D + tid];
            }
        }
        __syncthreads();
        // 2. compat [H,N]
        for (int idx = tid; idx < 800; idx += 512) {
            int hh = idx / 100, n = idx - hh*100;
            const float* kp = sh_hp + n*HPS + hh*16;
            const float* qp = sh_q + hh*16;
            double a0 = 0.0, a1 = 0.0;
#pragma unroll
            for (int d2 = 0; d2 < 16; d2 += 2) {
                a0 = fma((double)qp[d2],   (double)kp[d2],   a0);
                a1 = fma((double)qp[d2+1], (double)kp[d2+1], a1);
            }
            sh_c[idx] = sh_mask[n] ? NEGV : (float)((a0+a1) * NF);
        }
        __syncthreads();
        // 3. softmax, warps 0-7
        if (w < 8) {
            int head = w;
            double mx = -1e30;
            for (int n = lane; n < 100; n += 32) mx = fmax(mx, (double)sh_c[head*100 + n]);
#pragma unroll
            for (int off = 16; off; off >>= 1) mx = fmax(mx, __shfl_xor_sync(0xffffffffu, mx, off));
            double sum = 0.0, ev[4];
#pragma unroll
            for (int j = 0; j < 4; j++) {
                int n = lane + 32*j;
                if (n < 100) { ev[j] = exp((double)sh_c[head*100 + n] - mx); sum += ev[j]; }
                else ev[j] = 0.0;
            }
#pragma unroll
            for (int off = 16; off; off >>= 1) sum += __shfl_xor_sync(0xffffffffu, sum, off);
            double inv = 1.0 / sum;
#pragma unroll
            for (int j = 0; j < 4; j++) {
                int n = lane + 32*j;
                if (n < 100) sh_c[head*100 + n] = (float)(ev[j] * inv);
            }
        }
        __syncthreads();
        // 4. glimpse partials
        {
            int hh = dd >> 4;
            const float* pp = sh_c + hh*100 + part*25;
            const float* vp = sh_hp + (size_t)(part*25) * HPS + D + dd;
            double a0 = 0.0, a1 = 0.0;
#pragma unroll 4
            for (int n = 0; n < 24; n += 2) {
                a0 = fma((double)pp[n],   (double)vp[(n)*HPS],   a0);
                a1 = fma((double)pp[n+1], (double)vp[(n+1)*HPS], a1);
            }
            a0 = fma((double)pp[24], (double)vp[24*HPS], a0);
            sh_part[tid] = (float)(a0 + a1);
        }
        __syncthreads();
        if (tid < 128) sh_g[tid] = sh_part[tid] + sh_part[tid+128] + sh_part[tid+256] + sh_part[tid+384];
        __syncthreads();
        // 5. g2 partials
        {
            int k0 = part * 32;
            double a0=0, a1=0;
#pragma unroll 4
            for (int k = 0; k < 32; k += 2) {
                a0 = fma((double)sh_g[k0+k],   (double)sh_wout[(k0+k)*D + dd],   a0);
                a1 = fma((double)sh_g[k0+k+1], (double)sh_wout[(k0+k+1)*D + dd], a1);
            }
            sh_part[tid] = (float)(a0 + a1);
        }
        __syncthreads();
        if (tid < 128) sh_g2[tid] = sh_part[tid] + sh_part[tid+128] + sh_part[tid+256] + sh_part[tid+384];
        __syncthreads();
        // 6. logits partials
        if (dd < 100) {
            int k0 = part * 32;
            const float* lp = sh_hp + dd*HPS + 2*D + k0;
            double a0=0, a1=0;
#pragma unroll 4
            for (int k = 0; k < 32; k += 2) {
                a0 = fma((double)sh_g2[k0+k],   (double)lp[k],   a0);
                a1 = fma((double)sh_g2[k0+k+1], (double)lp[k+1], a1);
            }
            sh_part[tid] = (float)(a0 + a1);
        }
        __syncthreads();
        if (tid < 100) {
            double a = (double)sh_part[tid] + (double)sh_part[tid+128]
                     + (double)sh_part[tid+256] + (double)sh_part[tid+384];
            sh_lg[tid] = sh_mask[tid] ? NEGV : (float)(tanh(a * NF) * CLIPV);
        }
        __syncthreads();
        // 7. argmax + logsumexp, warp 0
        if (w == 0) {
            float mx = -1e30f; int mi = N + 1;
            for (int n = lane; n < N; n += 32) {
                float v = sh_lg[n];
                if (v > mx) { mx = v; mi = n; }
            }
#pragma unroll
            for (int off = 16; off; off >>= 1) {
                float om = __shfl_xor_sync(0xffffffffu, mx, off);
                int   oi = __shfl_xor_sync(0xffffffffu, mi, off);
                if (om > mx || (om == mx && oi < mi)) { mx = om; mi = oi; }
            }
            double sum = 0.0;
            for (int n = lane; n < N; n += 32) sum += exp((double)sh_lg[n] - (double)mx);
#pragma unroll
            for (int off = 16; off; off >>= 1) sum += __shfl_xor_sync(0xffffffffu, sum, off);
            if (lane == 0) {
                double lse = (double)mx + log(sum);
                sh_ll[0] += (double)sh_lg[mi] - lse;
                sh_mask[mi] = 1;
                sh_ctrl[1] = mi;
                if (s == 0) sh_ctrl[0] = mi;
                sh_pi[s] = mi;
                out[2*B + b*N + s] = (float)mi;
            }
        }
        __syncthreads();
    }
    // tour cost (closed cycle)
    if (tid < N) {
        int a = sh_pi[tid], c = sh_pi[(tid + 1) % N];
        double dx = (double)x[(b*N + a)*2]     - (double)x[(b*N + c)*2];
        double dy = (double)x[(b*N + a)*2 + 1] - (double)x[(b*N + c)*2 + 1];
        sh_lg[tid] = (float)sqrt(dx*dx + dy*dy);
    }
    __syncthreads();
    if (tid == 0) {
        double cst = 0.0;
        for (int t = 0; t < N; t++) cst += (double)sh_lg[t];
        out[b] = (float)cst;
        out[B + b] = (float)sh_ll[0];
    }
}

// ---------------------------------------------------------------------------
extern "C" void kernel_launch(void* const* d_in, const int* in_sizes, int n_in,
                              void* d_out, int out_size) {
    const float* x        = (const float*)d_in[0];
    const float* init_W   = (const float*)d_in[1];
    const float* init_b   = (const float*)d_in[2];
    const float* qkv_W    = (const float*)d_in[3];
    const float* out_W    = (const float*)d_in[4];
    const float* bn1      = (const float*)d_in[5];
    const float* bn2      = (const float*)d_in[6];
    const float* ff1_W    = (const float*)d_in[7];
    const float* ff1_b    = (const float*)d_in[8];
    const float* ff2_W    = (const float*)d_in[9];
    const float* ff2_b    = (const float*)d_in[10];
    const float* Wph      = (const float*)d_in[11];
    const float* nodes_W  = (const float*)d_in[12];
    const float* fixed_W  = (const float*)d_in[13];
    const float* step_W   = (const float*)d_in[14];
    const float* pout_W   = (const float*)d_in[15];
    float* out = (float*)d_out;

    cudaFuncSetAttribute(decode_kernel, cudaFuncAttributeMaxDynamicSharedMemorySize,
                         DEC_SMEM_BYTES + 128);
    cudaFuncSetAttribute(attn_kernel, cudaFuncAttributeMaxDynamicSharedMemorySize,
                         ATTN_SMEM_BYTES + 128);

    float *p_h, *p_3d, *p_ff, *p_o, *p_s, *p_ef, *p_ed;
    cudaGetSymbolAddress((void**)&p_h,  g_h);
    cudaGetSymbolAddress((void**)&p_3d, g_3d);
    cudaGetSymbolAddress((void**)&p_ff, g_ff);
    cudaGetSymbolAddress((void**)&p_o,  g_o);
    cudaGetSymbolAddress((void**)&p_s,  g_s);
    cudaGetSymbolAddress((void**)&p_ef, g_ef);
    cudaGetSymbolAddress((void**)&p_ed, g_ed);

    const int EW = 256;
    int egrid = (M_ROWS * D + EW - 1) / EW;

    init_embed_kernel<<<egrid, EW>>>(x, init_W, init_b);
    wphw_kernel<<<1, 128>>>(Wph, step_W);

    for (int l = 0; l < 2; l++) {
        gemm32_kernel<<<dim3(TD/128, M_ROWS/128), 256>>>(
            p_h, qkv_W + (size_t)l*D*TD, nullptr, nullptr, p_3d, M_ROWS, D, TD, 0);
        attn_kernel<<<B*H, 256, ATTN_SMEM_BYTES + 128>>>(p_3d, p_o);
        gemm32_kernel<<<dim3(D/128, M_ROWS/128), 256>>>(
            p_o, out_W + (size_t)l*D*D, nullptr, p_h, p_s, M_ROWS, D, D, 0);
        bn_stats1_kernel<<<128, 256>>>(p_s);
        bn_stats2_kernel<<<1, 128>>>();
        bn_apply_kernel<<<egrid, EW>>>(p_s, bn1 + (size_t)l*2*D, p_h);
        gemm32_kernel<<<dim3(FF/128, M_ROWS/128), 256>>>(
            p_h, ff1_W + (size_t)l*D*FF, ff1_b + (size_t)l*FF, nullptr, p_ff, M_ROWS, D, FF, 1);
        gemm32_kernel<<<dim3(D/128, M_ROWS/128), 256>>>(
            p_ff, ff2_W + (size_t)l*FF*D, ff2_b + (size_t)l*D, p_h, p_s, M_ROWS, FF, D, 0);
        bn_stats1_kernel<<<128, 256>>>(p_s);
        bn_stats2_kernel<<<1, 128>>>();
        bn_apply_kernel<<<egrid, EW>>>(p_s, bn2 + (size_t)l*2*D, p_h);
    }

    // decoder precompute
    gemm32_kernel<<<dim3(TD/128, M_ROWS/128), 256>>>(
        p_h, nodes_W, nullptr, nullptr, p_3d, M_ROWS, D, TD, 0);
    gemm32_kernel<<<dim3(D/128, M_ROWS/128), 256>>>(
        p_h, step_W, nullptr, nullptr, p_ef, M_ROWS, D, D, 0);
    gemm32_kernel<<<dim3(D/128, M_ROWS/128), 256>>>(
        p_h, step_W + (size_t)D*D, nullptr, nullptr, p_ed, M_ROWS, D, D, 0);
    meanfix_kernel<<<B, D>>>(fixed_W);

    decode_kernel<<<B, 512, DEC_SMEM_BYTES + 128>>>(x, pout_W, out);
}

// round 7
// speedup vs baseline: 2.9093x; 1.3127x over previous
#include <cuda_runtime.h>
#include <math.h>
#include <stdint.h>

// Problem constants
#define B 512
#define N 100
#define D 128
#define H 8
#define DK 16
#define FF 512
#define TD 384          // 3*D
#define M_ROWS (B*N)    // 51200
#define NEGV -1e9f
#define CLIPV 10.0

static __device__ float g_h [ (size_t)M_ROWS * D ];     // hidden state
static __device__ float g_3d[ (size_t)M_ROWS * TD ];    // qkv / hp scratch
static __device__ float g_ff[ (size_t)M_ROWS * FF ];    // ff1 output
static __device__ float g_o [ (size_t)M_ROWS * D ];     // attention output
static __device__ float g_s [ (size_t)M_ROWS * D ];     // pre-BN (residual sum)
static __device__ float g_ef[ (size_t)M_ROWS * D ];     // h @ Wstep[0:128]
static __device__ float g_ed[ (size_t)M_ROWS * D ];     // h @ Wstep[128:256]
static __device__ double g_part[2][128*128];            // BN partial sums
static __device__ double g_mean[D], g_rstd[D];
static __device__ double g_wphw[D];                     // Wph @ Wstep
static __device__ float g_fc[B*D], g_q0[B*D];           // fixed_ctx, step-0 query

// ---------------------------------------------------------------------------
// h = x @ init_W + init_b
// ---------------------------------------------------------------------------
__global__ void init_embed_kernel(const float* __restrict__ x,
                                  const float* __restrict__ W,
                                  const float* __restrict__ bias) {
    int idx = blockIdx.x * blockDim.x + threadIdx.x;
    if (idx >= M_ROWS * D) return;
    int i = idx >> 7, d = idx & 127;
    double v = (double)x[i*2] * (double)W[d]
             + (double)x[i*2+1] * (double)W[D + d]
             + (double)bias[d];
    g_h[idx] = (float)v;
}

// ---------------------------------------------------------------------------
// fp32 tiled GEMM: C[M,Nc] = A[M,K] @ W[K,Nc] (+bias)(+res)(relu)
// BM=BN=128, BK=16, 256 threads, 8x8 per thread (4+4 split). Pure FFMA.
// ---------------------------------------------------------------------------
__global__ __launch_bounds__(256, 2)
void gemm32_kernel(const float* __restrict__ A, const float* __restrict__ W,
                   const float* __restrict__ bias, const float* __restrict__ res,
                   float* __restrict__ C, int M, int K, int Nc, int relu) {
    __shared__ float As[16][132];
    __shared__ float Bs[16][132];
    const int tid = threadIdx.x;
    const int tx = tid & 15, ty = tid >> 4;
    const int row0 = blockIdx.y * 128, col0 = blockIdx.x * 128;
    float acc[8][8];
#pragma unroll
    for (int i = 0; i < 8; i++)
#pragma unroll
        for (int j = 0; j < 8; j++) acc[i][j] = 0.f;

    for (int kt = 0; kt < K; kt += 16) {
#pragma unroll
        for (int p = 0; p < 2; p++) {
            int idx = tid + p*256;
            int r = idx >> 2, kc = (idx & 3) * 4;
            float4 v = *reinterpret_cast<const float4*>(&A[(size_t)(row0+r)*K + kt + kc]);
            As[kc+0][r] = v.x; As[kc+1][r] = v.y; As[kc+2][r] = v.z; As[kc+3][r] = v.w;
        }
#pragma unroll
        for (int p = 0; p < 2; p++) {
            int idx = tid + p*256;
            int kr = idx >> 5, c = (idx & 31) * 4;
            float4 v = *reinterpret_cast<const float4*>(&W[(size_t)(kt+kr)*Nc + col0 + c]);
            *reinterpret_cast<float4*>(&Bs[kr][c]) = v;
        }
        __syncthreads();
#pragma unroll
        for (int k = 0; k < 16; k++) {
            float a[8], bb[8];
            float4 a0 = *reinterpret_cast<const float4*>(&As[k][ty*4]);
            float4 a1 = *reinterpret_cast<const float4*>(&As[k][64 + ty*4]);
            float4 b0 = *reinterpret_cast<const float4*>(&Bs[k][tx*4]);
            float4 b1 = *reinterpret_cast<const float4*>(&Bs[k][64 + tx*4]);
            a[0]=a0.x;a[1]=a0.y;a[2]=a0.z;a[3]=a0.w;a[4]=a1.x;a[5]=a1.y;a[6]=a1.z;a[7]=a1.w;
            bb[0]=b0.x;bb[1]=b0.y;bb[2]=b0.z;bb[3]=b0.w;bb[4]=b1.x;bb[5]=b1.y;bb[6]=b1.z;bb[7]=b1.w;
#pragma unroll
            for (int i = 0; i < 8; i++)
#pragma unroll
                for (int j = 0; j < 8; j++) acc[i][j] = fmaf(a[i], bb[j], acc[i][j]);
        }
        __syncthreads();
    }
#pragma unroll
    for (int i = 0; i < 8; i++) {
        int r = row0 + ty*4 + (i < 4 ? i : 60 + i);
#pragma unroll
        for (int j = 0; j < 8; j++) {
            int c = col0 + tx*4 + (j < 4 ? j : 60 + j);
            float v = acc[i][j];
            if (bias) v += bias[c];
            if (res)  v += res[(size_t)r*Nc + c];
            if (relu) v = fmaxf(v, 0.f);
            C[(size_t)r*Nc + c] = v;
        }
    }
}

// ---------------------------------------------------------------------------
// Fused MHA v3: one block per (b,h). fp32 dots; exp in double.
// Phase 1+2 fused per warp-row: scores in regs -> softmax -> psh.
// Phase 3: O = P @ V, fp32.
// ---------------------------------------------------------------------------
#define ATTN_SMEM_BYTES ((3*1700 + 10000) * 4)
__global__ __launch_bounds__(256)
void attn_kernel(const float* __restrict__ qkv, float* __restrict__ o) {
    extern __shared__ float asm_[];
    float* qsh = asm_;            // 100*17
    float* ksh = qsh + 1700;      // 100*17
    float* vsh = ksh + 1700;      // 100*17
    float* psh = vsh + 1700;      // 100*100
    int bh = blockIdx.x;
    int b = bh >> 3, hh = bh & 7;
    int tid = threadIdx.x;
    for (int i = tid; i < 1600; i += 256) {
        int m = i >> 4, d = i & 15;
        const float* base = qkv + (size_t)(b*N + m) * TD + hh*16 + d;
        qsh[m*17 + d] = base[0];
        ksh[m*17 + d] = base[D];
        vsh[m*17 + d] = base[2*D];
    }
    __syncthreads();
    int w = tid >> 5, lane = tid & 31;
    // phase 1+2: per-row scores (fp32) + softmax (double exp), warp per row
    for (int n = w; n < 100; n += 8) {
        float qreg[16];
        const float* qp = qsh + n*17;
#pragma unroll
        for (int d = 0; d < 16; d++) qreg[d] = qp[d];   // broadcast loads
        float sc[4];
        float mx = -1e30f;
#pragma unroll
        for (int j = 0; j < 4; j++) {
            int m = lane + 32*j;
            if (m < 100) {
                const float* kp = ksh + m*17;
                float a0 = 0.f, a1 = 0.f;
#pragma unroll
                for (int d = 0; d < 16; d += 2) {
                    a0 = fmaf(qreg[d],   kp[d],   a0);
                    a1 = fmaf(qreg[d+1], kp[d+1], a1);
                }
                sc[j] = (a0 + a1) * 0.25f;
                mx = fmaxf(mx, sc[j]);
            } else sc[j] = -1e30f;
        }
#pragma unroll
        for (int off = 16; off; off >>= 1) mx = fmaxf(mx, __shfl_xor_sync(0xffffffffu, mx, off));
        double sum = 0.0, ev[4];
#pragma unroll
        for (int j = 0; j < 4; j++) {
            int m = lane + 32*j;
            if (m < 100) { ev[j] = exp((double)(sc[j] - mx)); sum += ev[j]; }
            else ev[j] = 0.0;
        }
#pragma unroll
        for (int off = 16; off; off >>= 1) sum += __shfl_xor_sync(0xffffffffu, sum, off);
        double inv = 1.0 / sum;
#pragma unroll
        for (int j = 0; j < 4; j++) {
            int m = lane + 32*j;
            if (m < 100) psh[n*100 + m] = (float)(ev[j] * inv);
        }
    }
    __syncthreads();
    // phase 3: O = P @ V (fp32)
    for (int idx = tid; idx < 1600; idx += 256) {
        int n = idx >> 4, dk = idx & 15;
        const float* pp = psh + n*100;
        const float* vp = vsh + dk;
        float a0 = 0.f, a1 = 0.f;
#pragma unroll 4
        for (int m = 0; m < 100; m += 2) {
            a0 = fmaf(pp[m],   vp[(m)*17],   a0);
            a1 = fmaf(pp[m+1], vp[(m+1)*17], a1);
        }
        o[(size_t)(b*N + n) * D + hh*16 + dk] = a0 + a1;
    }
}

// ---------------------------------------------------------------------------
// BatchNorm, two-stage deterministic reduction (double).
// ---------------------------------------------------------------------------
__global__ void bn_stats1_kernel(const float* __restrict__ s) {
    __shared__ double ssum[256], ssq[256];
    int p = blockIdx.x, tid = threadIdx.x;
    int c = tid & 127, roff = tid >> 7;
    double a = 0.0, q = 0.0;
    size_t base = (size_t)p * 400 * D;
    for (int r = roff; r < 400; r += 2) {
        double v = (double)s[base + (size_t)r * D + c];
        a += v; q = fma(v, v, q);
    }
    ssum[tid] = a; ssq[tid] = q;
    __syncthreads();
    if (tid < 128) {
        g_part[0][p*128 + tid] = ssum[tid] + ssum[tid+128];
        g_part[1][p*128 + tid] = ssq[tid]  + ssq[tid+128];
    }
}
__global__ void bn_stats2_kernel() {
    int c = threadIdx.x;
    double a = 0.0, q = 0.0;
    for (int p = 0; p < 128; p++) { a += g_part[0][p*128 + c]; q += g_part[1][p*128 + c]; }
    double mean = a * (1.0 / (double)M_ROWS);
    double var  = q * (1.0 / (double)M_ROWS) - mean*mean;
    g_mean[c] = mean;
    g_rstd[c] = 1.0 / sqrt(var + 1e-5);
}
__global__ void bn_apply_kernel(const float* __restrict__ s, const float* __restrict__ gb,
                                float* __restrict__ h) {
    int idx = blockIdx.x * blockDim.x + threadIdx.x;
    if (idx >= M_ROWS * D) return;
    int d = idx & 127;
    double v = (double)gb[d] * ((double)s[idx] - g_mean[d]) * g_rstd[d] + (double)gb[D + d];
    h[idx] = (float)v;
}

// ---------------------------------------------------------------------------
// wphw[d] = Wph @ Wstep (column d)
// ---------------------------------------------------------------------------
__global__ void wphw_kernel(const float* __restrict__ Wph, const float* __restrict__ Wstep) {
    int d = threadIdx.x;
    double a0 = 0.0, a1 = 0.0;
    for (int k = 0; k < 2*D; k += 2) {
        a0 = fma((double)Wph[k],   (double)Wstep[(k)*D + d],   a0);
        a1 = fma((double)Wph[k+1], (double)Wstep[(k+1)*D + d], a1);
    }
    g_wphw[d] = a0 + a1;
}

// ---------------------------------------------------------------------------
// Per-batch: hm = mean_n(h); fc = hm @ Wf; q0 = fc + wphw
// ---------------------------------------------------------------------------
__global__ void meanfix_kernel(const float* __restrict__ Wf) {
    __shared__ float sh[D];
    int b = blockIdx.x, d = threadIdx.x;
    double a = 0.0;
    for (int n = 0; n < N; n++) a += (double)g_h[(size_t)(b*N + n) * D + d];
    sh[d] = (float)(a * (1.0 / (double)N));
    __syncthreads();
    double fc = 0.0;
    for (int k = 0; k < D; k++) fc = fma((double)sh[k], (double)Wf[k*D + d], fc);
    g_fc[b*D + d] = (float)fc;
    g_q0[b*D + d] = (float)(fc + g_wphw[d]);
}

// ---------------------------------------------------------------------------
// Persistent greedy decode v3. 512 threads, 1 block/batch, 2 blocks/SM.
// smem: gK+gV only (stride 257); Wout and lK read from L2. fp32 accum,
// transcendentals in double.
// ---------------------------------------------------------------------------
#define HPS2 257
#define DEC_SMEM_BYTES (16 + (N*HPS2 + 128 + 128 + 800 + 128 + 128 + 512 + 100)*4 + 202*4)

__global__ __launch_bounds__(512, 2)
void decode_kernel(const float* __restrict__ x,
                   const float* __restrict__ Wout,
                   float* __restrict__ out) {
    extern __shared__ double dsm[];
    double* sh_ll  = dsm;                   // [1]
    float* sh_hp   = (float*)(dsm + 2);     // 100*257 (gK | gV)
    float* sh_q    = sh_hp + N*HPS2;        // 128
    float* sh_qb   = sh_q + D;              // 128
    float* sh_c    = sh_qb + D;             // 800
    float* sh_g    = sh_c + 800;            // 128
    float* sh_g2   = sh_g + D;              // 128
    float* sh_part = sh_g2 + D;             // 512
    float* sh_lg   = sh_part + 512;         // 100
    int*   sh_mask = (int*)(sh_lg + 100);   // 100
    int*   sh_pi   = sh_mask + 100;         // 100
    int*   sh_ctrl = sh_pi + 100;           // first, prev

    const float NF = 0.08838834764831843f;  // 1/sqrt(D)
    int b = blockIdx.x, tid = threadIdx.x;
    int w = tid >> 5, lane = tid & 31;
    int dd = tid & 127, part = tid >> 7;
    const float* lKg = g_3d + (size_t)b * (N*TD) + 2*D;   // lK rows, stride TD

    for (int i = tid; i < N*256; i += 512) {
        int n = i >> 8, j = i & 255;
        sh_hp[n*HPS2 + j] = g_3d[(size_t)b * (N*TD) + n*TD + j];
    }
    if (tid < N) sh_mask[tid] = 0;
    if (tid == 0) { sh_ll[0] = 0.0; sh_ctrl[0] = 0; sh_ctrl[1] = 0; }
    __syncthreads();

    for (int s = 0; s < N; s++) {
        // 1. q from precomputed tables
        if (tid < 128) {
            if (s == 0) {
                sh_q[tid] = g_q0[b*D + tid];
            } else {
                float qb;
                if (s == 1) {
                    qb = g_fc[b*D + tid] + g_ef[(size_t)(b*N + sh_ctrl[0]) * D + tid];
                    sh_qb[tid] = qb;
                } else qb = sh_qb[tid];
                sh_q[tid] = qb + g_ed[(size_t)(b*N + sh_ctrl[1]) * D + tid];
            }
        }
        __syncthreads();
        // 2. compat [H,N] (fp32)
        for (int idx = tid; idx < 800; idx += 512) {
            int hh = idx / 100, n = idx - hh*100;
            const float* kp = sh_hp + n*HPS2 + hh*16;
            const float* qp = sh_q + hh*16;
            float a0 = 0.f, a1 = 0.f;
#pragma unroll
            for (int d2 = 0; d2 < 16; d2 += 2) {
                a0 = fmaf(qp[d2],   kp[d2],   a0);
                a1 = fmaf(qp[d2+1], kp[d2+1], a1);
            }
            sh_c[idx] = sh_mask[n] ? NEGV : (a0 + a1) * NF;
        }
        __syncthreads();
        // 3. softmax, warps 0-7 (double exp)
        if (w < 8) {
            int head = w;
            float mx = -1e30f;
            for (int n = lane; n < 100; n += 32) mx = fmaxf(mx, sh_c[head*100 + n]);
#pragma unroll
            for (int off = 16; off; off >>= 1) mx = fmaxf(mx, __shfl_xor_sync(0xffffffffu, mx, off));
            double sum = 0.0, ev[4];
#pragma unroll
            for (int j = 0; j < 4; j++) {
                int n = lane + 32*j;
                if (n < 100) { ev[j] = exp((double)(sh_c[head*100 + n] - mx)); sum += ev[j]; }
                else ev[j] = 0.0;
            }
#pragma unroll
            for (int off = 16; off; off >>= 1) sum += __shfl_xor_sync(0xffffffffu, sum, off);
            double inv = 1.0 / sum;
#pragma unroll
            for (int j = 0; j < 4; j++) {
                int n = lane + 32*j;
                if (n < 100) sh_c[head*100 + n] = (float)(ev[j] * inv);
            }
        }
        __syncthreads();
        // 4. glimpse partials (fp32)
        {
            int hh = dd >> 4;
            const float* pp = sh_c + hh*100 + part*25;
            const float* vp = sh_hp + (size_t)(part*25) * HPS2 + D + dd;
            float a0 = 0.f, a1 = 0.f;
#pragma unroll 4
            for (int n = 0; n < 24; n += 2) {
                a0 = fmaf(pp[n],   vp[(n)*HPS2],   a0);
                a1 = fmaf(pp[n+1], vp[(n+1)*HPS2], a1);
            }
            a0 = fmaf(pp[24], vp[24*HPS2], a0);
            sh_part[tid] = a0 + a1;
        }
        __syncthreads();
        if (tid < 128) sh_g[tid] = sh_part[tid] + sh_part[tid+128] + sh_part[tid+256] + sh_part[tid+384];
        __syncthreads();
        // 5. g2 partials: Wout from L2 (coalesced across dd)
        {
            int k0 = part * 32;
            float a0 = 0.f, a1 = 0.f;
#pragma unroll 4
            for (int k = 0; k < 32; k += 2) {
                a0 = fmaf(sh_g[k0+k],   __ldg(&Wout[(k0+k)*D + dd]),   a0);
                a1 = fmaf(sh_g[k0+k+1], __ldg(&Wout[(k0+k+1)*D + dd]), a1);
            }
            sh_part[tid] = a0 + a1;
        }
        __syncthreads();
        if (tid < 128) sh_g2[tid] = sh_part[tid] + sh_part[tid+128] + sh_part[tid+256] + sh_part[tid+384];
        __syncthreads();
        // 6. logits partials: lK from L2 (float4 per thread)
        if (dd < 100) {
            int k0 = part * 32;
            const float* lp = lKg + (size_t)dd * TD + k0;
            float a0 = 0.f, a1 = 0.f;
#pragma unroll
            for (int q4 = 0; q4 < 8; q4++) {
                float4 v = __ldg(reinterpret_cast<const float4*>(lp + q4*4));
                float4 g = *reinterpret_cast<const float4*>(&sh_g2[k0 + q4*4]);
                a0 = fmaf(g.x, v.x, a0); a1 = fmaf(g.y, v.y, a1);
                a0 = fmaf(g.z, v.z, a0); a1 = fmaf(g.w, v.w, a1);
            }
            sh_part[tid] = a0 + a1;
        }
        __syncthreads();
        if (tid < 100) {
            double a = (double)(sh_part[tid] + sh_part[tid+128] + sh_part[tid+256] + sh_part[tid+384]);
            sh_lg[tid] = sh_mask[tid] ? NEGV : (float)(tanh(a * (double)NF) * CLIPV);
        }
        __syncthreads();
        // 7. argmax + logsumexp, warp 0
        if (w == 0) {
            float mx = -1e30f; int mi = N + 1;
            for (int n = lane; n < N; n += 32) {
                float v = sh_lg[n];
                if (v > mx) { mx = v; mi = n; }
            }
#pragma unroll
            for (int off = 16; off; off >>= 1) {
                float om = __shfl_xor_sync(0xffffffffu, mx, off);
                int   oi = __shfl_xor_sync(0xffffffffu, mi, off);
                if (om > mx || (om == mx && oi < mi)) { mx = om; mi = oi; }
            }
            double sum = 0.0;
            for (int n = lane; n < N; n += 32) sum += exp((double)sh_lg[n] - (double)mx);
#pragma unroll
            for (int off = 16; off; off >>= 1) sum += __shfl_xor_sync(0xffffffffu, sum, off);
            if (lane == 0) {
                double lse = (double)mx + log(sum);
                sh_ll[0] += (double)sh_lg[mi] - lse;
                sh_mask[mi] = 1;
                sh_ctrl[1] = mi;
                if (s == 0) sh_ctrl[0] = mi;
                sh_pi[s] = mi;
                out[2*B + b*N + s] = (float)mi;
            }
        }
        __syncthreads();
    }
    // tour cost (closed cycle)
    if (tid < N) {
        int a = sh_pi[tid], c = sh_pi[(tid + 1) % N];
        double dx = (double)x[(b*N + a)*2]     - (double)x[(b*N + c)*2];
        double dy = (double)x[(b*N + a)*2 + 1] - (double)x[(b*N + c)*2 + 1];
        sh_lg[tid] = (float)sqrt(dx*dx + dy*dy);
    }
    __syncthreads();
    if (tid == 0) {
        double cst = 0.0;
        for (int t = 0; t < N; t++) cst += (double)sh_lg[t];
        out[b] = (float)cst;
        out[B + b] = (float)sh_ll[0];
    }
}

// ---------------------------------------------------------------------------
extern "C" void kernel_launch(void* const* d_in, const int* in_sizes, int n_in,
                              void* d_out, int out_size) {
    const float* x        = (const float*)d_in[0];
    const float* init_W   = (const float*)d_in[1];
    const float* init_b   = (const float*)d_in[2];
    const float* qkv_W    = (const float*)d_in[3];
    const float* out_W    = (const float*)d_in[4];
    const float* bn1      = (const float*)d_in[5];
    const float* bn2      = (const float*)d_in[6];
    const float* ff1_W    = (const float*)d_in[7];
    const float* ff1_b    = (const float*)d_in[8];
    const float* ff2_W    = (const float*)d_in[9];
    const float* ff2_b    = (const float*)d_in[10];
    const float* Wph      = (const float*)d_in[11];
    const float* nodes_W  = (const float*)d_in[12];
    const float* fixed_W  = (const float*)d_in[13];
    const float* step_W   = (const float*)d_in[14];
    const float* pout_W   = (const float*)d_in[15];
    float* out = (float*)d_out;

    cudaFuncSetAttribute(decode_kernel, cudaFuncAttributeMaxDynamicSharedMemorySize,
                         DEC_SMEM_BYTES + 128);
    cudaFuncSetAttribute(attn_kernel, cudaFuncAttributeMaxDynamicSharedMemorySize,
                         ATTN_SMEM_BYTES + 128);

    float *p_h, *p_3d, *p_ff, *p_o, *p_s, *p_ef, *p_ed;
    cudaGetSymbolAddress((void**)&p_h,  g_h);
    cudaGetSymbolAddress((void**)&p_3d, g_3d);
    cudaGetSymbolAddress((void**)&p_ff, g_ff);
    cudaGetSymbolAddress((void**)&p_o,  g_o);
    cudaGetSymbolAddress((void**)&p_s,  g_s);
    cudaGetSymbolAddress((void**)&p_ef, g_ef);
    cudaGetSymbolAddress((void**)&p_ed, g_ed);

    const int EW = 256;
    int egrid = (M_ROWS * D + EW - 1) / EW;

    init_embed_kernel<<<egrid, EW>>>(x, init_W, init_b);
    wphw_kernel<<<1, 128>>>(Wph, step_W);

    for (int l = 0; l < 2; l++) {
        gemm32_kernel<<<dim3(TD/128, M_ROWS/128), 256>>>(
            p_h, qkv_W + (size_t)l*D*TD, nullptr, nullptr, p_3d, M_ROWS, D, TD, 0);
        attn_kernel<<<B*H, 256, ATTN_SMEM_BYTES + 128>>>(p_3d, p_o);
        gemm32_kernel<<<dim3(D/128, M_ROWS/128), 256>>>(
            p_o, out_W + (size_t)l*D*D, nullptr, p_h, p_s, M_ROWS, D, D, 0);
        bn_stats1_kernel<<<128, 256>>>(p_s);
        bn_stats2_kernel<<<1, 128>>>();
        bn_apply_kernel<<<egrid, EW>>>(p_s, bn1 + (size_t)l*2*D, p_h);
        gemm32_kernel<<<dim3(FF/128, M_ROWS/128), 256>>>(
            p_h, ff1_W + (size_t)l*D*FF, ff1_b + (size_t)l*FF, nullptr, p_ff, M_ROWS, D, FF, 1);
        gemm32_kernel<<<dim3(D/128, M_ROWS/128), 256>>>(
            p_ff, ff2_W + (size_t)l*FF*D, ff2_b + (size_t)l*D, p_h, p_s, M_ROWS, FF, D, 0);
        bn_stats1_kernel<<<128, 256>>>(p_s);
        bn_stats2_kernel<<<1, 128>>>();
        bn_apply_kernel<<<egrid, EW>>>(p_s, bn2 + (size_t)l*2*D, p_h);
    }

    // decoder precompute
    gemm32_kernel<<<dim3(TD/128, M_ROWS/128), 256>>>(
        p_h, nodes_W, nullptr, nullptr, p_3d, M_ROWS, D, TD, 0);
    gemm32_kernel<<<dim3(D/128, M_ROWS/128), 256>>>(
        p_h, step_W, nullptr, nullptr, p_ef, M_ROWS, D, D, 0);
    gemm32_kernel<<<dim3(D/128, M_ROWS/128), 256>>>(
        p_h, step_W + (size_t)D*D, nullptr, nullptr, p_ed, M_ROWS, D, D, 0);
    meanfix_kernel<<<B, D>>>(fixed_W);

    decode_kernel<<<B, 512, DEC_SMEM_BYTES + 128>>>(x, pout_W, out);
}